// round 13
// baseline (speedup 1.0000x reference)
#include <cuda_runtime.h>
#include <math.h>
#include <cstdint>

#define T_N  4096
#define EMB  384
#define HID  256
#define NH   4
#define HD   64
#define MD   32
#define S0   33
#define NS   4063

#if defined(__CUDA_ARCH_FEAT_SM103_ALL) || defined(__CUDA_ARCH_FEAT_SM100_ALL) || defined(__CUDA_ARCH_FEAT_SM101_ALL)
#define HAS_TC 1
#else
#define HAS_TC 0
#endif

__device__ float g_h  [T_N * HID];
__device__ float g_x  [T_N * HID];
__device__ float g_Wh [T_N * HID];
__device__ float g_src[NH * T_N];
__device__ float g_dst[NH * T_N];
__device__ float g_scores[NS];
__device__ float g_cosf[NS];
__device__ float g_aw[NS];

__device__ __forceinline__ float warpSum(float v) {
    #pragma unroll
    for (int o = 16; o; o >>= 1) v += __shfl_xor_sync(0xffffffffu, v, o);
    return v;
}
__device__ __forceinline__ float warpMax(float v) {
    #pragma unroll
    for (int o = 16; o; o >>= 1) v = fmaxf(v, __shfl_xor_sync(0xffffffffu, v, o));
    return v;
}
__device__ float blockSum256(float v) {
    __shared__ float sh[8];
    int w = threadIdx.x >> 5, l = threadIdx.x & 31;
    v = warpSum(v);
    if (l == 0) sh[w] = v;
    __syncthreads();
    float s = (threadIdx.x < 8) ? sh[threadIdx.x] : 0.f;
    if (w == 0) { s = warpSum(s); if (l == 0) sh[0] = s; }
    __syncthreads();
    float r = sh[0];
    __syncthreads();
    return r;
}

__device__ __forceinline__ uint32_t s2u(const void* p) {
    uint32_t a;
    asm("{ .reg .u64 t; cvta.to.shared.u64 t, %1; cvt.u32.u64 %0, t; }"
        : "=r"(a) : "l"(p));
    return a;
}
__device__ __forceinline__ float ex2f(float x) {
    float r;
    asm("ex2.approx.f32 %0, %1;" : "=f"(r) : "f"(x));
    return r;
}

#if HAS_TC
__device__ __forceinline__ uint32_t elect_one() {
    uint32_t pred;
    asm volatile("{\n\t.reg .pred p;\n\telect.sync _|p, 0xFFFFFFFF;\n\t"
                 "selp.b32 %0, 1, 0, p;\n\t}" : "=r"(pred));
    return pred;
}
__device__ __forceinline__ void mbar_init(uint32_t addr, uint32_t cnt) {
    asm volatile("mbarrier.init.shared.b64 [%0], %1;" :: "r"(addr), "r"(cnt) : "memory");
}
__device__ __forceinline__ void mbar_wait(uint32_t addr, uint32_t parity) {
    asm volatile(
        "{\n\t.reg .pred P;\n\t"
        "WL%=:\n\t"
        "mbarrier.try_wait.parity.acquire.cta.shared::cta.b64 P, [%0], %1, 0x989680;\n\t"
        "@P bra WD%=;\n\t"
        "bra WL%=;\n\t"
        "WD%=:\n\t}"
        :: "r"(addr), "r"(parity) : "memory");
}
__device__ __forceinline__ void sts_tf32(uint32_t addr, float v) {
    uint32_t t;
    asm("cvt.rn.tf32.f32 %0, %1;" : "=r"(t) : "f"(v));
    asm volatile("st.shared.b32 [%0], %1;" :: "r"(addr), "r"(t) : "memory");
}
__device__ __forceinline__ void sts4_tf32(uint32_t addr, float4 v) {
    uint32_t a, b, c, d;
    asm("cvt.rn.tf32.f32 %0, %1;" : "=r"(a) : "f"(v.x));
    asm("cvt.rn.tf32.f32 %0, %1;" : "=r"(b) : "f"(v.y));
    asm("cvt.rn.tf32.f32 %0, %1;" : "=r"(c) : "f"(v.z));
    asm("cvt.rn.tf32.f32 %0, %1;" : "=r"(d) : "f"(v.w));
    asm volatile("st.shared.v4.b32 [%0], {%1, %2, %3, %4};"
                 :: "r"(addr), "r"(a), "r"(b), "r"(c), "r"(d) : "memory");
}
__device__ __forceinline__ void mma_tf32_ss(uint32_t d_tmem, uint64_t a_desc,
                                            uint64_t b_desc, uint32_t idesc,
                                            uint32_t en) {
    asm volatile(
        "{\n\t.reg .pred p;\n\tsetp.ne.u32 p, %4, 0;\n\t"
        "tcgen05.mma.cta_group::1.kind::tf32 [%0], %1, %2, %3, {%5, %5, %5, %5}, p;\n\t}"
        :: "r"(d_tmem), "l"(a_desc), "l"(b_desc), "r"(idesc), "r"(en), "r"(0u)
        : "memory");
}
__device__ __forceinline__ void tc_commit(uint32_t mbar) {
    asm volatile(
        "tcgen05.commit.cta_group::1.mbarrier::arrive::one.shared::cluster.b64 [%0];"
        :: "r"(mbar) : "memory");
}
#define TC_LD_X32(r, tmem_addr) \
    asm volatile( \
        "tcgen05.ld.sync.aligned.32x32b.x32.b32 " \
        "{%0, %1, %2, %3, %4, %5, %6, %7, " \
        " %8, %9, %10, %11, %12, %13, %14, %15, " \
        " %16, %17, %18, %19, %20, %21, %22, %23, " \
        " %24, %25, %26, %27, %28, %29, %30, %31}, [%32];" \
        : "=r"((r)[0]),  "=r"((r)[1]),  "=r"((r)[2]),  "=r"((r)[3]), \
          "=r"((r)[4]),  "=r"((r)[5]),  "=r"((r)[6]),  "=r"((r)[7]), \
          "=r"((r)[8]),  "=r"((r)[9]),  "=r"((r)[10]), "=r"((r)[11]), \
          "=r"((r)[12]), "=r"((r)[13]), "=r"((r)[14]), "=r"((r)[15]), \
          "=r"((r)[16]), "=r"((r)[17]), "=r"((r)[18]), "=r"((r)[19]), \
          "=r"((r)[20]), "=r"((r)[21]), "=r"((r)[22]), "=r"((r)[23]), \
          "=r"((r)[24]), "=r"((r)[25]), "=r"((r)[26]), "=r"((r)[27]), \
          "=r"((r)[28]), "=r"((r)[29]), "=r"((r)[30]), "=r"((r)[31]) \
        : "r"(tmem_addr))
#endif // HAS_TC

#define DESC_BASE ((2ull << 61) | (1ull << 46) | (64ull << 32) | (1ull << 16))
#define TF32_IDESC ((1u << 4) | (2u << 7) | (2u << 10) | (8u << 17) | (8u << 24))

// attn smem: 4-deep ring
#define SM_PB(b) ((b) * 16384)
#define SM_BB(b) (65536 + (b) * 8192)
#define SM_TPTR  98304
#define SM_MB(b) (98320 + (b) * 8)
#define SM_ZF    98368
#define SM_TOTAL (98880 + 1024)

// gemm_tc smem: 4-deep ring
#define GM_AB(b)  ((b) * 16384)
#define GM_BB(b)  (65536 + (b) * 8192)
#define GM_TPTR   98304
#define GM_MB(b)  (98320 + (b) * 8)
#define GM_BIAS   98368
#define GM_GA     98624
#define GM_TOTAL  (99136 + 1024)

// ============== tcgen05 tf32 GEMM, 4-deep ring, prefetch-first ==============
template<int K>
__global__ void __launch_bounds__(256) gemm_tc(const float* __restrict__ A,
                                               const float* __restrict__ Wt,
                                               const float* __restrict__ bias,
                                               float* __restrict__ C,
                                               int doRelu,
                                               const float* __restrict__ ga)
{
    extern __shared__ char dsm[];
    uint32_t raw = s2u(dsm);
    uint32_t base = (raw + 1023u) & ~1023u;
    char* smc = dsm + (base - raw);

    int tid = threadIdx.x, w = tid >> 5, lane = tid & 31;
    int cb = blockIdx.x & 3;
    int r0 = (blockIdx.x >> 2) * 128;
    int c0 = cb * 64;
    const int NC = K / 32;

#if HAS_TC
    if (w == 0)
        asm volatile("tcgen05.alloc.cta_group::1.sync.aligned.shared::cta.b32 [%0], %1;"
                     :: "r"(base + GM_TPTR), "r"(64u) : "memory");
    if (tid == 0) {
        #pragma unroll
        for (int b = 0; b < 4; b++) mbar_init(base + GM_MB(b), 1);
    }
    if (tid < 64) ((float*)(smc + GM_BIAS))[tid] = bias ? bias[c0 + tid] : 0.f;
    if (ga && tid < 128) ((float*)(smc + GM_GA))[tid] = ga[cb * 2 * HD + tid];
    __syncthreads();
    uint32_t tmem;
    asm volatile("ld.shared.b32 %0, [%1];" : "=r"(tmem) : "r"(base + GM_TPTR));

    uint32_t aoff[4];
    const float4* aptr[4];
    float4 av4[2][4];
    #pragma unroll
    for (int q = 0; q < 4; q++) {
        int idx = tid + q * 256;
        int m = idx >> 3, k4 = (idx & 7) * 4;
        aoff[q] = (uint32_t)(m * 128) + (((uint32_t)(k4 * 4)) ^ (uint32_t)((m & 7) << 4));
        aptr[q] = (const float4*)(A + (size_t)(r0 + m) * K + k4);
        av4[0][q] = aptr[q][0];
        aptr[q] += 8;           // -> chunk 1
    }
    uint32_t boff[2];
    const float4* bptr[2];
    float4 bv4[2][2];
    #pragma unroll
    for (int q = 0; q < 2; q++) {
        int idx = tid + q * 256;
        int n = idx >> 3, k4 = (idx & 7) * 4;
        boff[q] = (uint32_t)(n * 128) + (((uint32_t)(k4 * 4)) ^ (uint32_t)((n & 7) << 4));
        bptr[q] = (const float4*)(Wt + (size_t)(c0 + n) * K + k4);
        bv4[0][q] = bptr[q][0];
        bptr[q] += 8;
    }

    int wp0 = 0, wp1 = 0, wp2 = 0, wp3 = 0;
    #pragma unroll
    for (int t = 0; t < NC; t++) {
        const int cur = t & 1, nxt = cur ^ 1;
        const int b = t & 3;
        uint32_t Ab = base + GM_AB(b);
        uint32_t Bb = base + GM_BB(b);
        uint32_t mb = base + GM_MB(b);

        // 1) issue next chunk's loads first (fly during wait+staging)
        if (t < NC - 1) {
            #pragma unroll
            for (int q = 0; q < 4; q++) { av4[nxt][q] = aptr[q][0]; aptr[q] += 8; }
            #pragma unroll
            for (int q = 0; q < 2; q++) { bv4[nxt][q] = bptr[q][0]; bptr[q] += 8; }
        }

        // 2) wait for MMA of chunk t-4 on this buffer
        if (t >= 4) {
            if (b == 0)      { mbar_wait(base + GM_MB(0), wp0); wp0 ^= 1; }
            else if (b == 1) { mbar_wait(base + GM_MB(1), wp1); wp1 ^= 1; }
            else if (b == 2) { mbar_wait(base + GM_MB(2), wp2); wp2 ^= 1; }
            else             { mbar_wait(base + GM_MB(3), wp3); wp3 ^= 1; }
        }

        // 3) stage current chunk
        #pragma unroll
        for (int q = 0; q < 4; q++) sts4_tf32(Ab + aoff[q], av4[cur][q]);
        #pragma unroll
        for (int q = 0; q < 2; q++) sts4_tf32(Bb + boff[q], bv4[cur][q]);

        asm volatile("fence.proxy.async.shared::cta;" ::: "memory");
        __syncthreads();

        if (w == 0 && elect_one()) {
            uint64_t ad = DESC_BASE | ((uint64_t)(Ab >> 4) & 0x3FFF);
            uint64_t bd = DESC_BASE | ((uint64_t)(Bb >> 4) & 0x3FFF);
            #pragma unroll
            for (int c = 0; c < 4; c++)
                mma_tf32_ss(tmem, ad + c * 2, bd + c * 2, TF32_IDESC,
                            (t > 0 || c > 0) ? 1u : 0u);
            tc_commit(mb);
        }
    }

    // last chunk (NC-1; NC=8 or 12 -> buffer 3) commit covers all MMAs
    mbar_wait(base + GM_MB(3), wp3);
    asm volatile("tcgen05.fence::after_thread_sync;" ::: "memory");

    if (w < 4) {
        uint32_t dr[64];
        TC_LD_X32(dr, tmem);
        TC_LD_X32(dr + 32, tmem + 32);
        asm volatile("tcgen05.wait::ld.sync.aligned;" ::: "memory");
        int row = w * 32 + lane;
        const float* sb = (const float*)(smc + GM_BIAS);
        float4* op = (float4*)&C[(size_t)(r0 + row) * HID + c0];
        float vals[64];
        #pragma unroll
        for (int q = 0; q < 16; q++) {
            float4 o;
            o.x = __uint_as_float(dr[4 * q])     + sb[4 * q];
            o.y = __uint_as_float(dr[4 * q + 1]) + sb[4 * q + 1];
            o.z = __uint_as_float(dr[4 * q + 2]) + sb[4 * q + 2];
            o.w = __uint_as_float(dr[4 * q + 3]) + sb[4 * q + 3];
            if (doRelu) {
                o.x = fmaxf(o.x, 0.f); o.y = fmaxf(o.y, 0.f);
                o.z = fmaxf(o.z, 0.f); o.w = fmaxf(o.w, 0.f);
            }
            vals[4 * q] = o.x; vals[4 * q + 1] = o.y;
            vals[4 * q + 2] = o.z; vals[4 * q + 3] = o.w;
            op[q] = o;
        }
        if (ga) {
            const float* as = (const float*)(smc + GM_GA);
            const float* ad = as + HD;
            float ssum = 0.f, dsum = 0.f;
            #pragma unroll
            for (int c = 0; c < 64; c++) {
                ssum += vals[c] * as[c];
                dsum += vals[c] * ad[c];
            }
            g_src[cb * T_N + r0 + row] = ssum;
            g_dst[cb * T_N + r0 + row] = dsum;
        }
    }
    __syncthreads();
    if (w == 0) {
        asm volatile("tcgen05.relinquish_alloc_permit.cta_group::1.sync.aligned;");
        asm volatile("tcgen05.dealloc.cta_group::1.sync.aligned.b32 %0, %1;"
                     :: "r"(tmem), "r"(64u));
    }
#else
    int c = tid & 63, rh = tid >> 6;
    for (int m = rh * 32; m < rh * 32 + 32; m++) {
        float acc = 0.f;
        const float* ap = A + (size_t)(r0 + m) * K;
        const float* wp2 = Wt + (size_t)(c0 + c) * K;
        for (int k = 0; k < K; k++) acc += ap[k] * wp2[k];
        float b = bias ? bias[c0 + c] : 0.f;
        float v = acc + b;
        if (doRelu) v = fmaxf(v, 0.f);
        C[(size_t)(r0 + m) * HID + c0 + c] = v;
    }
    __syncthreads();
    if (ga && tid < 128) {
        int row = tid;
        const float* cp = &C[(size_t)(r0 + row) * HID + c0];
        float ssum = 0.f, dsum = 0.f;
        for (int cc = 0; cc < 64; cc++) {
            ssum += cp[cc] * ga[cb * 2 * HD + cc];
            dsum += cp[cc] * ga[cb * 2 * HD + HD + cc];
        }
        g_src[cb * T_N + r0 + row] = ssum;
        g_dst[cb * T_N + r0 + row] = dsum;
    }
#endif
}

__global__ void __launch_bounds__(256) cos_update()
{
    __shared__ float q[HID];
    int tid = threadIdx.x;
    q[tid] = g_h[tid];
    __syncthreads();
    float qn = blockSum256(q[tid] * q[tid]);
    float qinv = 1.f / (sqrtf(qn) + 1e-8f);
    int w = tid >> 5, l = tid & 31;
    int j = blockIdx.x * 8 + w;
    if (j >= NS) return;
    float* s = &g_h[(size_t)(S0 + j) * HID];
    float sv[8];
    float qs = 0.f, ss = 0.f;
    #pragma unroll
    for (int e = 0; e < 8; e++) {
        float x = s[l + 32 * e];
        sv[e] = x;
        qs += q[l + 32 * e] * x;
        ss += x * x;
    }
    qs = warpSum(qs);
    ss = warpSum(ss);
    float cs = qs * qinv / (sqrtf(ss) + 1e-8f);
    #pragma unroll
    for (int e = 0; e < 8; e++)
        s[l + 32 * e] = sv[e] + 0.8f * q[l + 32 * e] * cs;
}

__global__ void __launch_bounds__(256) ln2_k(const float* __restrict__ scale,
                                             const float* __restrict__ bias)
{
    __shared__ float sc[HID], bi[HID];
    int tid = threadIdx.x, w = tid >> 5, l = tid & 31;
    sc[tid] = scale[tid];
    bi[tid] = bias[tid];
    __syncthreads();
    int row = blockIdx.x * 8 + w;
    const float* hp = &g_h[(size_t)row * HID];
    float v[8];
    float s = 0.f;
    #pragma unroll
    for (int e = 0; e < 8; e++) { v[e] = hp[l + 32 * e]; s += v[e]; }
    float mu = warpSum(s) * (1.f / HID);
    float ss = 0.f;
    #pragma unroll
    for (int e = 0; e < 8; e++) { v[e] -= mu; ss += v[e] * v[e]; }
    float rs = rsqrtf(warpSum(ss) * (1.f / HID) + 1e-5f);
    float* xp = &g_x[(size_t)row * HID];
    #pragma unroll
    for (int e = 0; e < 8; e++)
        xp[l + 32 * e] = v[e] * rs * sc[l + 32 * e] + bi[l + 32 * e];
}

// ============== attention: prefetch-first, 4-deep ring, fused combine ==============
__global__ void __launch_bounds__(256) attn_tc(const int* __restrict__ adj)
{
    extern __shared__ char dsm[];
    uint32_t raw = s2u(dsm);
    uint32_t base = (raw + 1023u) & ~1023u;
    char* smc = dsm + (base - raw);
    float* zfin = (float*)(smc + SM_ZF);

    int tid = threadIdx.x, w = tid >> 5, lane = tid & 31;
    int h = blockIdx.x & 3;
    int i0 = (blockIdx.x >> 2) * 128;

    const float L2E = 1.44269504f;
    float srcv[16], zacc[16];
    #pragma unroll
    for (int i = 0; i < 16; i++) {
        srcv[i] = g_src[h * T_N + i0 + w * 16 + i];
        zacc[i] = 0.f;
    }

    const int* adjp = adj + (size_t)(i0 + w * 16) * T_N + lane;
    const float* dstp = g_dst + h * T_N + lane;
    const float* whp0 = g_Wh + h * 64;
    const int NT = T_N / 32;

#if HAS_TC
    if (w == 0)
        asm volatile("tcgen05.alloc.cta_group::1.sync.aligned.shared::cta.b32 [%0], %1;"
                     :: "r"(base + SM_TPTR), "r"(64u) : "memory");
    if (tid == 0) {
        #pragma unroll
        for (int b = 0; b < 4; b++) mbar_init(base + SM_MB(b), 1);
    }
    __syncthreads();
    uint32_t tmem;
    asm volatile("ld.shared.b32 %0, [%1];" : "=r"(tmem) : "r"(base + SM_TPTR));

    uint32_t boffq[8];
    const float* bptr[8];
    #pragma unroll
    for (int q = 0; q < 8; q++) {
        int idx = tid + q * 256;
        int n = idx & 63, k = idx >> 6;
        boffq[q] = (uint32_t)(n * 128) + (((uint32_t)(k * 4)) ^ (uint32_t)((n & 7) << 4));
        bptr[q] = whp0 + (size_t)k * HID + n;
    }

    // preload tile 0 into set 0; pointers advance to tile 1
    int   av[2][16];
    float dval[2];
    float bv[2][8];
    #pragma unroll
    for (int i = 0; i < 16; i++) av[0][i] = adjp[(size_t)i * T_N];
    dval[0] = dstp[0];
    #pragma unroll
    for (int q = 0; q < 8; q++) { bv[0][q] = bptr[q][0]; bptr[q] += 32 * HID; }

    int wpar0 = 0, wpar1 = 0, wpar2 = 0, wpar3 = 0;

    for (int tb = 0; tb < NT; tb += 4) {
        #pragma unroll
        for (int b = 0; b < 4; b++) {
            const int t = tb + b;
            const int cur = b & 1, nxt = cur ^ 1;   // tb is even multiple of 4
            uint32_t Pb = base + SM_PB(b);
            uint32_t Bb = base + SM_BB(b);
            uint32_t mb = base + SM_MB(b);

            // 1) issue prefetch for tile t+1 (overlaps wait + staging + P-gen)
            if (t < NT - 1) {
                int j1 = (t + 1) * 32;
                #pragma unroll
                for (int i = 0; i < 16; i++) av[nxt][i] = adjp[(size_t)i * T_N + j1];
                dval[nxt] = dstp[j1];
                #pragma unroll
                for (int q = 0; q < 8; q++) { bv[nxt][q] = bptr[q][0]; bptr[q] += 32 * HID; }
            }

            // 2) wait for MMA of tile t-4 on this buffer
            if (tb > 0) {
                if (b == 0)      { mbar_wait(mb, wpar0); wpar0 ^= 1; }
                else if (b == 1) { mbar_wait(mb, wpar1); wpar1 ^= 1; }
                else if (b == 2) { mbar_wait(mb, wpar2); wpar2 ^= 1; }
                else             { mbar_wait(mb, wpar3); wpar3 ^= 1; }
            }

            // 3) stage B tile
            #pragma unroll
            for (int q = 0; q < 8; q++) sts_tf32(Bb + boffq[q], bv[cur][q]);

            // 4) P tile: p = adj ? exp2(lrelu(src+dst)*log2e) : 0
            float dv = dval[cur];
            #pragma unroll
            for (int i = 0; i < 16; i++) {
                float ev = srcv[i] + dv;
                ev = fmaxf(ev, 0.2f * ev);
                float p = ex2f(ev * L2E);
                p = av[cur][i] ? p : 0.f;
                zacc[i] += p;
                sts_tf32(Pb + (uint32_t)((w * 16 + i) * 128)
                            + ((uint32_t)(lane * 4) ^ (uint32_t)((i & 7) << 4)), p);
            }

            asm volatile("fence.proxy.async.shared::cta;" ::: "memory");
            __syncthreads();

            if (w == 0 && elect_one()) {
                uint64_t ad = DESC_BASE | ((uint64_t)(Pb >> 4) & 0x3FFF);
                uint64_t bd = DESC_BASE | ((uint64_t)(Bb >> 4) & 0x3FFF);
                #pragma unroll
                for (int c = 0; c < 4; c++)
                    mma_tf32_ss(tmem, ad + c * 2, bd + c * 2, TF32_IDESC,
                                (t > 0 || c > 0) ? 1u : 0u);
                tc_commit(mb);
            }
        }
    }

    #pragma unroll
    for (int i = 0; i < 16; i++) {
        float z = warpSum(zacc[i]);
        if (lane == i) zfin[w * 16 + i] = 1.f / z;
    }
    __syncthreads();

    mbar_wait(base + SM_MB(3), wpar3);
    asm volatile("tcgen05.fence::after_thread_sync;" ::: "memory");

    if (w < 4) {
        uint32_t dr[64];
        TC_LD_X32(dr, tmem);
        TC_LD_X32(dr + 32, tmem + 32);
        asm volatile("tcgen05.wait::ld.sync.aligned;" ::: "memory");
        int row = w * 32 + lane;
        float zi = zfin[row];
        float4* hp = (float4*)&g_h[(size_t)(i0 + row) * HID + h * 64];
        #pragma unroll
        for (int q = 0; q < 16; q++) {
            float4 old = hp[q];
            float4 o;
            o.x = 0.5f * fmaxf(__uint_as_float(dr[4 * q])     * zi, 0.f) + 0.5f * old.x;
            o.y = 0.5f * fmaxf(__uint_as_float(dr[4 * q + 1]) * zi, 0.f) + 0.5f * old.y;
            o.z = 0.5f * fmaxf(__uint_as_float(dr[4 * q + 2]) * zi, 0.f) + 0.5f * old.z;
            o.w = 0.5f * fmaxf(__uint_as_float(dr[4 * q + 3]) * zi, 0.f) + 0.5f * old.w;
            hp[q] = o;
        }
    }
    __syncthreads();
    if (w == 0) {
        asm volatile("tcgen05.relinquish_alloc_permit.cta_group::1.sync.aligned;");
        asm volatile("tcgen05.dealloc.cta_group::1.sync.aligned.b32 %0, %1;"
                     :: "r"(tmem), "r"(64u));
    }
#else
    // SIMT fallback (non-sm_103a passes only)
    float* P = (float*)smc;
    int col = tid & 63, rhalf = tid >> 6;
    float acc[32];
    #pragma unroll
    for (int r = 0; r < 32; r++) acc[r] = 0.f;
    int avs[16];
    #pragma unroll
    for (int i = 0; i < 16; i++) avs[i] = adjp[(size_t)i * T_N];
    float dvs = dstp[0];
    __syncthreads();

    for (int t = 0; t < NT; t++) {
        int j0 = t * 32;
        #pragma unroll
        for (int i = 0; i < 16; i++) {
            float ev = srcv[i] + dvs;
            ev = fmaxf(ev, 0.2f * ev);
            float p = ex2f(ev * L2E);
            p = avs[i] ? p : 0.f;
            zacc[i] += p;
            P[(w * 16 + i) * 33 + lane] = p;
        }
        if (t < NT - 1) {
            #pragma unroll
            for (int i = 0; i < 16; i++) avs[i] = adjp[(size_t)i * T_N + j0 + 32];
            dvs = dstp[j0 + 32];
        }
        __syncthreads();
        const float* whc = whp0 + (size_t)j0 * HID + col;
        #pragma unroll 4
        for (int jl = 0; jl < 32; jl++) {
            float b = whc[(size_t)jl * HID];
            const float* Pc = P + (rhalf * 32) * 33 + jl;
            #pragma unroll
            for (int r = 0; r < 32; r++) acc[r] += Pc[r * 33] * b;
        }
        __syncthreads();
    }

    #pragma unroll
    for (int i = 0; i < 16; i++) {
        float z = warpSum(zacc[i]);
        if (lane == i) zfin[w * 16 + i] = 1.f / z;
    }
    __syncthreads();
    #pragma unroll
    for (int r = 0; r < 32; r++) {
        int row = rhalf * 32 + r;
        size_t gi = (size_t)(i0 + row) * HID + h * 64 + col;
        float o = acc[r] * zfin[row];
        g_h[gi] = 0.5f * fmaxf(o, 0.f) + 0.5f * g_h[gi];
    }
#endif
}

__global__ void __launch_bounds__(256) scorecos_k()
{
    __shared__ float q[HID];
    int tid = threadIdx.x;
    q[tid] = g_h[tid];
    __syncthreads();
    float qn = blockSum256(q[tid] * q[tid]);
    float qinv = 1.f / (sqrtf(qn) + 1e-8f);
    int w = tid >> 5, l = tid & 31;
    int j = blockIdx.x * 8 + w;
    if (j >= NS) return;
    const float* s = &g_h[(size_t)(S0 + j) * HID];
    float qs = 0.f, ss = 0.f;
    #pragma unroll
    for (int e = 0; e < 8; e++) {
        float x = s[l + 32 * e];
        qs += q[l + 32 * e] * x;
        ss += x * x;
    }
    qs = warpSum(qs);
    ss = warpSum(ss);
    if (l == 0) {
        g_scores[j] = qs * (1.0f / 16.0f);
        g_cosf[j] = qs * qinv / (sqrtf(ss) + 1e-8f);
    }
}

__global__ void __launch_bounds__(1024) softmax_k()
{
    __shared__ float sh[32];
    int tid = threadIdx.x, w = tid >> 5, l = tid & 31;

    float m = -1e30f;
    for (int i = tid; i < NS; i += 1024) m = fmaxf(m, g_scores[i]);
    m = warpMax(m);
    if (l == 0) sh[w] = m;
    __syncthreads();
    if (w == 0) { float mm = sh[l]; mm = warpMax(mm); if (l == 0) sh[0] = mm; }
    __syncthreads();
    m = sh[0];
    __syncthreads();

    float sum = 0.f;
    for (int i = tid; i < NS; i += 1024) {
        float e = __expf(g_scores[i] - m);
        g_aw[i] = e;
        sum += e;
    }
    sum = warpSum(sum);
    if (l == 0) sh[w] = sum;
    __syncthreads();
    if (w == 0) { float ss = sh[l]; ss = warpSum(ss); if (l == 0) sh[0] = ss; }
    __syncthreads();
    float inv = 1.f / sh[0];
    for (int i = tid; i < NS; i += 1024) g_aw[i] *= inv;
}

__global__ void __launch_bounds__(256) fusion_k(const float* __restrict__ fw,
                                                const float* __restrict__ fb,
                                                const float* __restrict__ ow,
                                                const float* __restrict__ obp,
                                                float* __restrict__ out)
{
    __shared__ float fws[256][33];
    __shared__ __align__(16) float feat_s[32][20];
    __shared__ float awv[16], cosv[16];
    __shared__ float red2[16][8];
    int tid = threadIdx.x;
    int w = tid >> 5, lane = tid & 31;
    int j0 = blockIdx.x * 16;

    if (tid < 16) {
        int j = j0 + tid;
        awv[tid]  = (j < NS) ? g_aw[j]   : 0.f;
        cosv[tid] = (j < NS) ? g_cosf[j] : 0.f;
    }
    __syncthreads();

    unsigned long long acc2[8];
    #pragma unroll
    for (int i = 0; i < 8; i++) acc2[i] = 0ull;
    int c = tid;

    for (int k0 = 0; k0 < 512; k0 += 32) {
        #pragma unroll 8
        for (int rr = 0; rr < 32; rr++)
            fws[w * 32 + rr][lane] = fw[(size_t)(w * 32 + rr) * 514 + k0 + lane];
        #pragma unroll
        for (int q = 0; q < 2; q++) {
            int idx = tid + q * 256;
            int r = idx >> 5, kk = idx & 31;
            int k = k0 + kk;
            int j = j0 + r;
            float v = 0.f;
            if (j < NS) {
                if (k < 256) v = g_h[(size_t)(S0 + j) * HID + k];
                else         v = g_h[k - 256] * (awv[r] + 0.5f);
            }
            feat_s[kk][r] = v;
        }
        __syncthreads();

        #pragma unroll 8
        for (int kk = 0; kk < 32; kk++) {
            float wv = fws[c][kk];
            unsigned long long wvd;
            asm("mov.b64 %0, {%1,%1};" : "=l"(wvd) : "r"(__float_as_uint(wv)));
            const ulonglong2* fp = (const ulonglong2*)&feat_s[kk][0];
            #pragma unroll
            for (int q = 0; q < 4; q++) {
                ulonglong2 fv = fp[q];
                asm("fma.rn.f32x2 %0, %1, %2, %0;" : "+l"(acc2[2*q  ]) : "l"(fv.x), "l"(wvd));
                asm("fma.rn.f32x2 %0, %1, %2, %0;" : "+l"(acc2[2*q+1]) : "l"(fv.y), "l"(wvd));
            }
        }
        __syncthreads();
    }

    float acc[16];
    #pragma unroll
    for (int q = 0; q < 8; q++) {
        acc[2*q]   = __uint_as_float((unsigned)(acc2[q] & 0xffffffffull));
        acc[2*q+1] = __uint_as_float((unsigned)(acc2[q] >> 32));
    }
    float w512 = fw[(size_t)c * 514 + 512];
    float w513 = fw[(size_t)c * 514 + 513];
    #pragma unroll
    for (int r = 0; r < 16; r++) acc[r] += w512 * cosv[r] + w513 * awv[r];

    float fbv = fb[c];
    float owv = ow[c];
    #pragma unroll
    for (int r = 0; r < 16; r++) {
        float gv = fmaxf(acc[r] + fbv, 0.f) * owv;
        gv = warpSum(gv);
        if (lane == 0) red2[r][w] = gv;
    }
    __syncthreads();
    if (tid < 16) {
        float s = 0.f;
        #pragma unroll
        for (int ww = 0; ww < 8; ww++) s += red2[tid][ww];
        int j = j0 + tid;
        if (j < NS) out[j] = s + obp[0] + 0.5f * cosv[tid];
    }
}

// ---------------- launch ----------------
extern "C" void kernel_launch(void* const* d_in, const int* in_sizes, int n_in,
                              void* d_out, int out_size)
{
    const float* emb    = (const float*)d_in[0];
    const int*   adj    = (const int*)  d_in[1];
    const float* proj_w = (const float*)d_in[3];
    const float* proj_b = (const float*)d_in[4];
    const float* ln_s   = (const float*)d_in[5];
    const float* ln_b   = (const float*)d_in[6];
    const float* gat_W  = (const float*)d_in[7];
    const float* gat_a  = (const float*)d_in[8];
    const float* fw     = (const float*)d_in[9];
    const float* fb     = (const float*)d_in[10];
    const float* ow     = (const float*)d_in[11];
    const float* ob     = (const float*)d_in[12];
    float* out = (float*)d_out;

    float *hP, *xP, *whP;
    cudaGetSymbolAddress((void**)&hP,  g_h);
    cudaGetSymbolAddress((void**)&xP,  g_x);
    cudaGetSymbolAddress((void**)&whP, g_Wh);

    cudaFuncSetAttribute(attn_tc, cudaFuncAttributeMaxDynamicSharedMemorySize, SM_TOTAL);
    cudaFuncSetAttribute(gemm_tc<EMB>, cudaFuncAttributeMaxDynamicSharedMemorySize, GM_TOTAL);
    cudaFuncSetAttribute(gemm_tc<HID>, cudaFuncAttributeMaxDynamicSharedMemorySize, GM_TOTAL);

    gemm_tc<EMB><<<(T_N / 128) * 4, 256, GM_TOTAL>>>(emb, proj_w, proj_b, hP, 1, nullptr);
    cos_update<<<(NS + 7) / 8, 256>>>();

    for (int L = 0; L < 2; L++) {
        ln2_k<<<T_N / 8, 256>>>(ln_s + L * HID, ln_b + L * HID);
        gemm_tc<HID><<<(T_N / 128) * 4, 256, GM_TOTAL>>>(xP, gat_W + (size_t)L * HID * HID,
                                                          nullptr, whP, 0,
                                                          gat_a + L * NH * 2 * HD);
        attn_tc<<<128, 256, SM_TOTAL>>>(adj);
    }

    scorecos_k<<<(NS + 7) / 8, 256>>>();
    softmax_k<<<1, 1024>>>();
    fusion_k<<<(NS + 15) / 16, 256>>>(fw, fb, ow, ob, out);
}

// round 14
// speedup vs baseline: 1.4875x; 1.4875x over previous
#include <cuda_runtime.h>
#include <math.h>
#include <cstdint>

#define T_N  4096
#define EMB  384
#define HID  256
#define NH   4
#define HD   64
#define MD   32
#define S0   33
#define NS   4063

#if defined(__CUDA_ARCH_FEAT_SM103_ALL) || defined(__CUDA_ARCH_FEAT_SM100_ALL) || defined(__CUDA_ARCH_FEAT_SM101_ALL)
#define HAS_TC 1
#else
#define HAS_TC 0
#endif

__device__ float g_h  [T_N * HID];
__device__ float g_Wh [T_N * HID];
__device__ float g_src[NH * T_N];
__device__ float g_dst[NH * T_N];
__device__ float g_lnmu[T_N];
__device__ float g_lnrs[T_N];
__device__ float g_scores[NS];
__device__ float g_cosf[NS];
__device__ float g_aw[NS];

__device__ __forceinline__ float warpSum(float v) {
    #pragma unroll
    for (int o = 16; o; o >>= 1) v += __shfl_xor_sync(0xffffffffu, v, o);
    return v;
}
__device__ __forceinline__ float warpMax(float v) {
    #pragma unroll
    for (int o = 16; o; o >>= 1) v = fmaxf(v, __shfl_xor_sync(0xffffffffu, v, o));
    return v;
}
__device__ float blockSum256(float v) {
    __shared__ float sh[8];
    int w = threadIdx.x >> 5, l = threadIdx.x & 31;
    v = warpSum(v);
    if (l == 0) sh[w] = v;
    __syncthreads();
    float s = (threadIdx.x < 8) ? sh[threadIdx.x] : 0.f;
    if (w == 0) { s = warpSum(s); if (l == 0) sh[0] = s; }
    __syncthreads();
    float r = sh[0];
    __syncthreads();
    return r;
}

__device__ __forceinline__ uint32_t s2u(const void* p) {
    uint32_t a;
    asm("{ .reg .u64 t; cvta.to.shared.u64 t, %1; cvt.u32.u64 %0, t; }"
        : "=r"(a) : "l"(p));
    return a;
}
__device__ __forceinline__ float ex2f(float x) {
    float r;
    asm("ex2.approx.f32 %0, %1;" : "=f"(r) : "f"(x));
    return r;
}

#if HAS_TC
__device__ __forceinline__ uint32_t elect_one() {
    uint32_t pred;
    asm volatile("{\n\t.reg .pred p;\n\telect.sync _|p, 0xFFFFFFFF;\n\t"
                 "selp.b32 %0, 1, 0, p;\n\t}" : "=r"(pred));
    return pred;
}
__device__ __forceinline__ void mbar_init(uint32_t addr, uint32_t cnt) {
    asm volatile("mbarrier.init.shared.b64 [%0], %1;" :: "r"(addr), "r"(cnt) : "memory");
}
__device__ __forceinline__ void mbar_wait(uint32_t addr, uint32_t parity) {
    asm volatile(
        "{\n\t.reg .pred P;\n\t"
        "WL%=:\n\t"
        "mbarrier.try_wait.parity.acquire.cta.shared::cta.b64 P, [%0], %1, 0x989680;\n\t"
        "@P bra WD%=;\n\t"
        "bra WL%=;\n\t"
        "WD%=:\n\t}"
        :: "r"(addr), "r"(parity) : "memory");
}
__device__ __forceinline__ void sts_tf32(uint32_t addr, float v) {
    uint32_t t;
    asm("cvt.rn.tf32.f32 %0, %1;" : "=r"(t) : "f"(v));
    asm volatile("st.shared.b32 [%0], %1;" :: "r"(addr), "r"(t) : "memory");
}
__device__ __forceinline__ void sts4_tf32(uint32_t addr, float4 v) {
    uint32_t a, b, c, d;
    asm("cvt.rn.tf32.f32 %0, %1;" : "=r"(a) : "f"(v.x));
    asm("cvt.rn.tf32.f32 %0, %1;" : "=r"(b) : "f"(v.y));
    asm("cvt.rn.tf32.f32 %0, %1;" : "=r"(c) : "f"(v.z));
    asm("cvt.rn.tf32.f32 %0, %1;" : "=r"(d) : "f"(v.w));
    asm volatile("st.shared.v4.b32 [%0], {%1, %2, %3, %4};"
                 :: "r"(addr), "r"(a), "r"(b), "r"(c), "r"(d) : "memory");
}
__device__ __forceinline__ void mma_tf32_ss(uint32_t d_tmem, uint64_t a_desc,
                                            uint64_t b_desc, uint32_t idesc,
                                            uint32_t en) {
    asm volatile(
        "{\n\t.reg .pred p;\n\tsetp.ne.u32 p, %4, 0;\n\t"
        "tcgen05.mma.cta_group::1.kind::tf32 [%0], %1, %2, %3, {%5, %5, %5, %5}, p;\n\t}"
        :: "r"(d_tmem), "l"(a_desc), "l"(b_desc), "r"(idesc), "r"(en), "r"(0u)
        : "memory");
}
__device__ __forceinline__ void tc_commit(uint32_t mbar) {
    asm volatile(
        "tcgen05.commit.cta_group::1.mbarrier::arrive::one.shared::cluster.b64 [%0];"
        :: "r"(mbar) : "memory");
}
#define TC_LD_X32(r, tmem_addr) \
    asm volatile( \
        "tcgen05.ld.sync.aligned.32x32b.x32.b32 " \
        "{%0, %1, %2, %3, %4, %5, %6, %7, " \
        " %8, %9, %10, %11, %12, %13, %14, %15, " \
        " %16, %17, %18, %19, %20, %21, %22, %23, " \
        " %24, %25, %26, %27, %28, %29, %30, %31}, [%32];" \
        : "=r"((r)[0]),  "=r"((r)[1]),  "=r"((r)[2]),  "=r"((r)[3]), \
          "=r"((r)[4]),  "=r"((r)[5]),  "=r"((r)[6]),  "=r"((r)[7]), \
          "=r"((r)[8]),  "=r"((r)[9]),  "=r"((r)[10]), "=r"((r)[11]), \
          "=r"((r)[12]), "=r"((r)[13]), "=r"((r)[14]), "=r"((r)[15]), \
          "=r"((r)[16]), "=r"((r)[17]), "=r"((r)[18]), "=r"((r)[19]), \
          "=r"((r)[20]), "=r"((r)[21]), "=r"((r)[22]), "=r"((r)[23]), \
          "=r"((r)[24]), "=r"((r)[25]), "=r"((r)[26]), "=r"((r)[27]), \
          "=r"((r)[28]), "=r"((r)[29]), "=r"((r)[30]), "=r"((r)[31]) \
        : "r"(tmem_addr))
#endif // HAS_TC

#define DESC_BASE ((2ull << 61) | (1ull << 46) | (64ull << 32) | (1ull << 16))
#define TF32_IDESC ((1u << 4) | (2u << 7) | (2u << 10) | (8u << 17) | (8u << 24))

// attn smem: 4-deep ring (R12 layout)
#define SM_PB(b) ((b) * 16384)
#define SM_BB(b) (65536 + (b) * 8192)
#define SM_TPTR  98304
#define SM_MB(b) (98320 + (b) * 8)
#define SM_ZF    98368
#define SM_TOTAL (98880 + 1024)

// gemm_tc smem (R12 2-deep layout + LN scale/bias)
#define GM_AB(b)  ((b) * 16384)
#define GM_BB(b)  (32768 + (b) * 8192)
#define GM_TPTR   49152
#define GM_MB(b)  (49168 + (b) * 8)
#define GM_BIAS   49184
#define GM_GA     49440
#define GM_LNS    49952
#define GM_LNB    50976
#define GM_TOTAL  (52000 + 1024)

// ============== per-row LN stats (mean, rstd) ==============
__global__ void __launch_bounds__(256) ln_stats()
{
    int tid = threadIdx.x, w = tid >> 5, l = tid & 31;
    int row = blockIdx.x * 8 + w;
    const float* hp = &g_h[(size_t)row * HID];
    float v[8];
    float s = 0.f;
    #pragma unroll
    for (int e = 0; e < 8; e++) { v[e] = hp[l + 32 * e]; s += v[e]; }
    float mu = warpSum(s) * (1.f / HID);
    float ss = 0.f;
    #pragma unroll
    for (int e = 0; e < 8; e++) { float d = v[e] - mu; ss += d * d; }
    float rs = rsqrtf(warpSum(ss) * (1.f / HID) + 1e-5f);
    if (l == 0) { g_lnmu[row] = mu; g_lnrs[row] = rs; }
}

// ============== tcgen05 tf32 GEMM (R12 structure) + optional LN-on-A + src/dst epilogue ==============
// C[r0:+128, c0:+64] = LN(A)[128,K] @ Wt[64,K]^T
template<int K>
__global__ void __launch_bounds__(256) gemm_tc(const float* __restrict__ A,
                                               const float* __restrict__ Wt,
                                               const float* __restrict__ bias,
                                               float* __restrict__ C,
                                               int doRelu,
                                               const float* __restrict__ ga,
                                               const float* __restrict__ lnS,
                                               const float* __restrict__ lnB)
{
    extern __shared__ char dsm[];
    uint32_t raw = s2u(dsm);
    uint32_t base = (raw + 1023u) & ~1023u;
    char* smc = dsm + (base - raw);

    int tid = threadIdx.x, w = tid >> 5, lane = tid & 31;
    int cb = blockIdx.x & 3;
    int r0 = (blockIdx.x >> 2) * 128;
    int c0 = cb * 64;
    const int NC = K / 32;

#if HAS_TC
    if (w == 0)
        asm volatile("tcgen05.alloc.cta_group::1.sync.aligned.shared::cta.b32 [%0], %1;"
                     :: "r"(base + GM_TPTR), "r"(64u) : "memory");
    if (tid == 0) { mbar_init(base + GM_MB(0), 1); mbar_init(base + GM_MB(1), 1); }
    if (tid < 64) ((float*)(smc + GM_BIAS))[tid] = bias ? bias[c0 + tid] : 0.f;
    if (ga && tid < 128) ((float*)(smc + GM_GA))[tid] = ga[cb * 2 * HD + tid];
    if (lnS) {
        ((float*)(smc + GM_LNS))[tid] = lnS[tid & (HID - 1)];
        ((float*)(smc + GM_LNB))[tid] = lnB[tid & (HID - 1)];
    }
    __syncthreads();
    uint32_t tmem;
    asm volatile("ld.shared.b32 %0, [%1];" : "=r"(tmem) : "r"(base + GM_TPTR));

    uint32_t aoff[4];
    int ak4[4];
    const float4* aptr[4];
    float4 av4[4];
    float muv[4], rsv[4];
    #pragma unroll
    for (int q = 0; q < 4; q++) {
        int idx = tid + q * 256;
        int m = idx >> 3, k4 = (idx & 7) * 4;
        aoff[q] = (uint32_t)(m * 128) + (((uint32_t)(k4 * 4)) ^ (uint32_t)((m & 7) << 4));
        ak4[q] = k4;
        aptr[q] = (const float4*)(A + (size_t)(r0 + m) * K + k4);
        av4[q] = aptr[q][0];
        if (lnS) { muv[q] = g_lnmu[r0 + m]; rsv[q] = g_lnrs[r0 + m]; }
    }
    uint32_t boff[2];
    const float4* bptr[2];
    float4 bv4[2];
    #pragma unroll
    for (int q = 0; q < 2; q++) {
        int idx = tid + q * 256;
        int n = idx >> 3, k4 = (idx & 7) * 4;
        boff[q] = (uint32_t)(n * 128) + (((uint32_t)(k4 * 4)) ^ (uint32_t)((n & 7) << 4));
        bptr[q] = (const float4*)(Wt + (size_t)(c0 + n) * K + k4);
        bv4[q] = bptr[q][0];
    }

    int wp0 = 0, wp1 = 0;
    for (int t = 0; t < NC; t++) {
        int buf = t & 1;
        uint32_t Ab = base + GM_AB(buf);
        uint32_t Bb = base + GM_BB(buf);
        uint32_t mb = base + GM_MB(buf);

        if (t >= 2) {
            if (buf == 0) { mbar_wait(base + GM_MB(0), wp0); wp0 ^= 1; }
            else          { mbar_wait(base + GM_MB(1), wp1); wp1 ^= 1; }
        }

        #pragma unroll
        for (int q = 0; q < 4; q++) {
            float4 x = av4[q];
            if (lnS) {
                int k = t * 32 + ak4[q];
                float4 sc = *(const float4*)(smc + GM_LNS + (size_t)k * 4);
                float4 bi = *(const float4*)(smc + GM_LNB + (size_t)k * 4);
                x.x = (x.x - muv[q]) * rsv[q] * sc.x + bi.x;
                x.y = (x.y - muv[q]) * rsv[q] * sc.y + bi.y;
                x.z = (x.z - muv[q]) * rsv[q] * sc.z + bi.z;
                x.w = (x.w - muv[q]) * rsv[q] * sc.w + bi.w;
            }
            sts4_tf32(Ab + aoff[q], x);
        }
        #pragma unroll
        for (int q = 0; q < 2; q++) sts4_tf32(Bb + boff[q], bv4[q]);

        if (t < NC - 1) {
            #pragma unroll
            for (int q = 0; q < 4; q++) { aptr[q] += 8; av4[q] = aptr[q][0]; }
            #pragma unroll
            for (int q = 0; q < 2; q++) { bptr[q] += 8; bv4[q] = bptr[q][0]; }
        }

        asm volatile("fence.proxy.async.shared::cta;" ::: "memory");
        __syncthreads();

        if (w == 0 && elect_one()) {
            uint64_t ad = DESC_BASE | ((uint64_t)(Ab >> 4) & 0x3FFF);
            uint64_t bd = DESC_BASE | ((uint64_t)(Bb >> 4) & 0x3FFF);
            #pragma unroll
            for (int c = 0; c < 4; c++)
                mma_tf32_ss(tmem, ad + c * 2, bd + c * 2, TF32_IDESC,
                            (t > 0 || c > 0) ? 1u : 0u);
            tc_commit(mb);
        }
    }

    mbar_wait(base + GM_MB(1), wp1);
    asm volatile("tcgen05.fence::after_thread_sync;" ::: "memory");

    if (w < 4) {
        uint32_t dr[64];
        TC_LD_X32(dr, tmem);
        TC_LD_X32(dr + 32, tmem + 32);
        asm volatile("tcgen05.wait::ld.sync.aligned;" ::: "memory");
        int row = w * 32 + lane;
        const float* sb = (const float*)(smc + GM_BIAS);
        float4* op = (float4*)&C[(size_t)(r0 + row) * HID + c0];
        float vals[64];
        #pragma unroll
        for (int q = 0; q < 16; q++) {
            float4 o;
            o.x = __uint_as_float(dr[4 * q])     + sb[4 * q];
            o.y = __uint_as_float(dr[4 * q + 1]) + sb[4 * q + 1];
            o.z = __uint_as_float(dr[4 * q + 2]) + sb[4 * q + 2];
            o.w = __uint_as_float(dr[4 * q + 3]) + sb[4 * q + 3];
            if (doRelu) {
                o.x = fmaxf(o.x, 0.f); o.y = fmaxf(o.y, 0.f);
                o.z = fmaxf(o.z, 0.f); o.w = fmaxf(o.w, 0.f);
            }
            vals[4 * q] = o.x; vals[4 * q + 1] = o.y;
            vals[4 * q + 2] = o.z; vals[4 * q + 3] = o.w;
            op[q] = o;
        }
        if (ga) {
            const float* as = (const float*)(smc + GM_GA);
            const float* ad = as + HD;
            float ssum = 0.f, dsum = 0.f;
            #pragma unroll
            for (int c = 0; c < 64; c++) {
                ssum += vals[c] * as[c];
                dsum += vals[c] * ad[c];
            }
            g_src[cb * T_N + r0 + row] = ssum;
            g_dst[cb * T_N + r0 + row] = dsum;
        }
    }
    __syncthreads();
    if (w == 0) {
        asm volatile("tcgen05.relinquish_alloc_permit.cta_group::1.sync.aligned;");
        asm volatile("tcgen05.dealloc.cta_group::1.sync.aligned.b32 %0, %1;"
                     :: "r"(tmem), "r"(64u));
    }
#else
    // SIMT fallback (non-sm_103a passes only; never runs on GB300)
    int c = tid & 63, rh = tid >> 6;
    for (int m = rh * 32; m < rh * 32 + 32; m++) {
        float acc = 0.f;
        const float* ap = A + (size_t)(r0 + m) * K;
        const float* wp2 = Wt + (size_t)(c0 + c) * K;
        float mu = lnS ? g_lnmu[r0 + m] : 0.f;
        float rs = lnS ? g_lnrs[r0 + m] : 1.f;
        for (int k = 0; k < K; k++) {
            float a = ap[k];
            if (lnS) a = (a - mu) * rs * lnS[k] + lnB[k];
            acc += a * wp2[k];
        }
        float b = bias ? bias[c0 + c] : 0.f;
        float v = acc + b;
        if (doRelu) v = fmaxf(v, 0.f);
        C[(size_t)(r0 + m) * HID + c0 + c] = v;
    }
    __syncthreads();
    if (ga && tid < 128) {
        int row = tid;
        const float* cp = &C[(size_t)(r0 + row) * HID + c0];
        float ssum = 0.f, dsum = 0.f;
        for (int cc = 0; cc < 64; cc++) {
            ssum += cp[cc] * ga[cb * 2 * HD + cc];
            dsum += cp[cc] * ga[cb * 2 * HD + HD + cc];
        }
        g_src[cb * T_N + r0 + row] = ssum;
        g_dst[cb * T_N + r0 + row] = dsum;
    }
#endif
}

__global__ void __launch_bounds__(256) cos_update()
{
    __shared__ float q[HID];
    int tid = threadIdx.x;
    q[tid] = g_h[tid];
    __syncthreads();
    float qn = blockSum256(q[tid] * q[tid]);
    float qinv = 1.f / (sqrtf(qn) + 1e-8f);
    int w = tid >> 5, l = tid & 31;
    int j = blockIdx.x * 8 + w;
    if (j >= NS) return;
    float* s = &g_h[(size_t)(S0 + j) * HID];
    float sv[8];
    float qs = 0.f, ss = 0.f;
    #pragma unroll
    for (int e = 0; e < 8; e++) {
        float x = s[l + 32 * e];
        sv[e] = x;
        qs += q[l + 32 * e] * x;
        ss += x * x;
    }
    qs = warpSum(qs);
    ss = warpSum(ss);
    float cs = qs * qinv / (sqrtf(ss) + 1e-8f);
    #pragma unroll
    for (int e = 0; e < 8; e++)
        s[l + 32 * e] = sv[e] + 0.8f * q[l + 32 * e] * cs;
}

// ============== attention (R12 structure, unchanged) ==============
__global__ void __launch_bounds__(256) attn_tc(const int* __restrict__ adj)
{
    extern __shared__ char dsm[];
    uint32_t raw = s2u(dsm);
    uint32_t base = (raw + 1023u) & ~1023u;
    char* smc = dsm + (base - raw);
    float* zfin = (float*)(smc + SM_ZF);

    int tid = threadIdx.x, w = tid >> 5, lane = tid & 31;
    int h = blockIdx.x & 3;
    int i0 = (blockIdx.x >> 2) * 128;

    const float L2E = 1.44269504f;
    float srcv[16], zacc[16];
    #pragma unroll
    for (int i = 0; i < 16; i++) {
        srcv[i] = g_src[h * T_N + i0 + w * 16 + i];
        zacc[i] = 0.f;
    }

    const int* adjp = adj + (size_t)(i0 + w * 16) * T_N + lane;
    const float* dstp = g_dst + h * T_N + lane;
    const float* whp0 = g_Wh + h * 64;
    const int NT = T_N / 32;

    int av[16];
    float dval;
    #pragma unroll
    for (int i = 0; i < 16; i++) av[i] = adjp[(size_t)i * T_N];
    dval = dstp[0];

#if HAS_TC
    if (w == 0)
        asm volatile("tcgen05.alloc.cta_group::1.sync.aligned.shared::cta.b32 [%0], %1;"
                     :: "r"(base + SM_TPTR), "r"(64u) : "memory");
    if (tid == 0) {
        #pragma unroll
        for (int b = 0; b < 4; b++) mbar_init(base + SM_MB(b), 1);
    }
    __syncthreads();
    uint32_t tmem;
    asm volatile("ld.shared.b32 %0, [%1];" : "=r"(tmem) : "r"(base + SM_TPTR));

    uint32_t boffq[8];
    const float* bptr[8];
    #pragma unroll
    for (int q = 0; q < 8; q++) {
        int idx = tid + q * 256;
        int n = idx & 63, k = idx >> 6;
        boffq[q] = (uint32_t)(n * 128) + (((uint32_t)(k * 4)) ^ (uint32_t)((n & 7) << 4));
        bptr[q] = whp0 + (size_t)k * HID + n;
    }
    float bv[8];
    #pragma unroll
    for (int q = 0; q < 8; q++) bv[q] = bptr[q][0];

    int wpar0 = 0, wpar1 = 0, wpar2 = 0, wpar3 = 0;

    for (int tb = 0; tb < NT; tb += 4) {
        #pragma unroll
        for (int b = 0; b < 4; b++) {
            const int t = tb + b;
            uint32_t Pb = base + SM_PB(b);
            uint32_t Bb = base + SM_BB(b);
            uint32_t mb = base + SM_MB(b);

            if (tb > 0) {
                if (b == 0)      { mbar_wait(mb, wpar0); wpar0 ^= 1; }
                else if (b == 1) { mbar_wait(mb, wpar1); wpar1 ^= 1; }
                else if (b == 2) { mbar_wait(mb, wpar2); wpar2 ^= 1; }
                else             { mbar_wait(mb, wpar3); wpar3 ^= 1; }
            }

            #pragma unroll
            for (int q = 0; q < 8; q++) sts_tf32(Bb + boffq[q], bv[q]);

            #pragma unroll
            for (int i = 0; i < 16; i++) {
                float ev = srcv[i] + dval;
                ev = fmaxf(ev, 0.2f * ev);
                float p = ex2f(ev * L2E);
                p = av[i] ? p : 0.f;
                zacc[i] += p;
                sts_tf32(Pb + (uint32_t)((w * 16 + i) * 128)
                            + ((uint32_t)(lane * 4) ^ (uint32_t)((i & 7) << 4)), p);
            }

            if (t < NT - 1) {
                int j1 = (t + 1) * 32;
                #pragma unroll
                for (int i = 0; i < 16; i++) av[i] = adjp[(size_t)i * T_N + j1];
                dval = dstp[j1];
                #pragma unroll
                for (int q = 0; q < 8; q++) {
                    bptr[q] += 32 * HID;
                    bv[q] = bptr[q][0];
                }
            }

            asm volatile("fence.proxy.async.shared::cta;" ::: "memory");
            __syncthreads();

            if (w == 0 && elect_one()) {
                uint64_t ad = DESC_BASE | ((uint64_t)(Pb >> 4) & 0x3FFF);
                uint64_t bd = DESC_BASE | ((uint64_t)(Bb >> 4) & 0x3FFF);
                #pragma unroll
                for (int c = 0; c < 4; c++)
                    mma_tf32_ss(tmem, ad + c * 2, bd + c * 2, TF32_IDESC,
                                (t > 0 || c > 0) ? 1u : 0u);
                tc_commit(mb);
            }
        }
    }

    #pragma unroll
    for (int i = 0; i < 16; i++) {
        float z = warpSum(zacc[i]);
        if (lane == i) zfin[w * 16 + i] = 1.f / z;
    }
    __syncthreads();

    mbar_wait(base + SM_MB(3), wpar3);
    asm volatile("tcgen05.fence::after_thread_sync;" ::: "memory");

    if (w < 4) {
        uint32_t dr[64];
        TC_LD_X32(dr, tmem);
        TC_LD_X32(dr + 32, tmem + 32);
        asm volatile("tcgen05.wait::ld.sync.aligned;" ::: "memory");
        int row = w * 32 + lane;
        float zi = zfin[row];
        float4* hp = (float4*)&g_h[(size_t)(i0 + row) * HID + h * 64];
        #pragma unroll
        for (int q = 0; q < 16; q++) {
            float4 old = hp[q];
            float4 o;
            o.x = 0.5f * fmaxf(__uint_as_float(dr[4 * q])     * zi, 0.f) + 0.5f * old.x;
            o.y = 0.5f * fmaxf(__uint_as_float(dr[4 * q + 1]) * zi, 0.f) + 0.5f * old.y;
            o.z = 0.5f * fmaxf(__uint_as_float(dr[4 * q + 2]) * zi, 0.f) + 0.5f * old.z;
            o.w = 0.5f * fmaxf(__uint_as_float(dr[4 * q + 3]) * zi, 0.f) + 0.5f * old.w;
            hp[q] = o;
        }
    }
    __syncthreads();
    if (w == 0) {
        asm volatile("tcgen05.relinquish_alloc_permit.cta_group::1.sync.aligned;");
        asm volatile("tcgen05.dealloc.cta_group::1.sync.aligned.b32 %0, %1;"
                     :: "r"(tmem), "r"(64u));
    }
#else
    // SIMT fallback (non-sm_103a passes only)
    float* P = (float*)smc;
    int col = tid & 63, rhalf = tid >> 6;
    float acc[32];
    #pragma unroll
    for (int r = 0; r < 32; r++) acc[r] = 0.f;
    __syncthreads();

    for (int t = 0; t < NT; t++) {
        int j0 = t * 32;
        #pragma unroll
        for (int i = 0; i < 16; i++) {
            float ev = srcv[i] + dval;
            ev = fmaxf(ev, 0.2f * ev);
            float p = ex2f(ev * L2E);
            p = av[i] ? p : 0.f;
            zacc[i] += p;
            P[(w * 16 + i) * 33 + lane] = p;
        }
        if (t < NT - 1) {
            #pragma unroll
            for (int i = 0; i < 16; i++) av[i] = adjp[(size_t)i * T_N + j0 + 32];
            dval = dstp[j0 + 32];
        }
        __syncthreads();
        const float* whc = whp0 + (size_t)j0 * HID + col;
        #pragma unroll 4
        for (int jl = 0; jl < 32; jl++) {
            float b = whc[(size_t)jl * HID];
            const float* Pc = P + (rhalf * 32) * 33 + jl;
            #pragma unroll
            for (int r = 0; r < 32; r++) acc[r] += Pc[r * 33] * b;
        }
        __syncthreads();
    }

    #pragma unroll
    for (int i = 0; i < 16; i++) {
        float z = warpSum(zacc[i]);
        if (lane == i) zfin[w * 16 + i] = 1.f / z;
    }
    __syncthreads();
    #pragma unroll
    for (int r = 0; r < 32; r++) {
        int row = rhalf * 32 + r;
        size_t gi = (size_t)(i0 + row) * HID + h * 64 + col;
        float o = acc[r] * zfin[row];
        g_h[gi] = 0.5f * fmaxf(o, 0.f) + 0.5f * g_h[gi];
    }
#endif
}

__global__ void __launch_bounds__(256) scorecos_k()
{
    __shared__ float q[HID];
    int tid = threadIdx.x;
    q[tid] = g_h[tid];
    __syncthreads();
    float qn = blockSum256(q[tid] * q[tid]);
    float qinv = 1.f / (sqrtf(qn) + 1e-8f);
    int w = tid >> 5, l = tid & 31;
    int j = blockIdx.x * 8 + w;
    if (j >= NS) return;
    const float* s = &g_h[(size_t)(S0 + j) * HID];
    float qs = 0.f, ss = 0.f;
    #pragma unroll
    for (int e = 0; e < 8; e++) {
        float x = s[l + 32 * e];
        qs += q[l + 32 * e] * x;
        ss += x * x;
    }
    qs = warpSum(qs);
    ss = warpSum(ss);
    if (l == 0) {
        g_scores[j] = qs * (1.0f / 16.0f);
        g_cosf[j] = qs * qinv / (sqrtf(ss) + 1e-8f);
    }
}

__global__ void __launch_bounds__(1024) softmax_k()
{
    __shared__ float sh[32];
    int tid = threadIdx.x, w = tid >> 5, l = tid & 31;

    float m = -1e30f;
    for (int i = tid; i < NS; i += 1024) m = fmaxf(m, g_scores[i]);
    m = warpMax(m);
    if (l == 0) sh[w] = m;
    __syncthreads();
    if (w == 0) { float mm = sh[l]; mm = warpMax(mm); if (l == 0) sh[0] = mm; }
    __syncthreads();
    m = sh[0];
    __syncthreads();

    float sum = 0.f;
    for (int i = tid; i < NS; i += 1024) {
        float e = __expf(g_scores[i] - m);
        g_aw[i] = e;
        sum += e;
    }
    sum = warpSum(sum);
    if (l == 0) sh[w] = sum;
    __syncthreads();
    if (w == 0) { float ss = sh[l]; ss = warpSum(ss); if (l == 0) sh[0] = ss; }
    __syncthreads();
    float inv = 1.f / sh[0];
    for (int i = tid; i < NS; i += 1024) g_aw[i] *= inv;
}

__global__ void __launch_bounds__(256) fusion_k(const float* __restrict__ fw,
                                                const float* __restrict__ fb,
                                                const float* __restrict__ ow,
                                                const float* __restrict__ obp,
                                                float* __restrict__ out)
{
    __shared__ float fws[256][33];
    __shared__ __align__(16) float feat_s[32][20];
    __shared__ float awv[16], cosv[16];
    __shared__ float red2[16][8];
    int tid = threadIdx.x;
    int w = tid >> 5, lane = tid & 31;
    int j0 = blockIdx.x * 16;

    if (tid < 16) {
        int j = j0 + tid;
        awv[tid]  = (j < NS) ? g_aw[j]   : 0.f;
        cosv[tid] = (j < NS) ? g_cosf[j] : 0.f;
    }
    __syncthreads();

    unsigned long long acc2[8];
    #pragma unroll
    for (int i = 0; i < 8; i++) acc2[i] = 0ull;
    int c = tid;

    for (int k0 = 0; k0 < 512; k0 += 32) {
        #pragma unroll 8
        for (int rr = 0; rr < 32; rr++)
            fws[w * 32 + rr][lane] = fw[(size_t)(w * 32 + rr) * 514 + k0 + lane];
        #pragma unroll
        for (int q = 0; q < 2; q++) {
            int idx = tid + q * 256;
            int r = idx >> 5, kk = idx & 31;
            int k = k0 + kk;
            int j = j0 + r;
            float v = 0.f;
            if (j < NS) {
                if (k < 256) v = g_h[(size_t)(S0 + j) * HID + k];
                else         v = g_h[k - 256] * (awv[r] + 0.5f);
            }
            feat_s[kk][r] = v;
        }
        __syncthreads();

        #pragma unroll 8
        for (int kk = 0; kk < 32; kk++) {
            float wv = fws[c][kk];
            unsigned long long wvd;
            asm("mov.b64 %0, {%1,%1};" : "=l"(wvd) : "r"(__float_as_uint(wv)));
            const ulonglong2* fp = (const ulonglong2*)&feat_s[kk][0];
            #pragma unroll
            for (int q = 0; q < 4; q++) {
                ulonglong2 fv = fp[q];
                asm("fma.rn.f32x2 %0, %1, %2, %0;" : "+l"(acc2[2*q  ]) : "l"(fv.x), "l"(wvd));
                asm("fma.rn.f32x2 %0, %1, %2, %0;" : "+l"(acc2[2*q+1]) : "l"(fv.y), "l"(wvd));
            }
        }
        __syncthreads();
    }

    float acc[16];
    #pragma unroll
    for (int q = 0; q < 8; q++) {
        acc[2*q]   = __uint_as_float((unsigned)(acc2[q] & 0xffffffffull));
        acc[2*q+1] = __uint_as_float((unsigned)(acc2[q] >> 32));
    }
    float w512 = fw[(size_t)c * 514 + 512];
    float w513 = fw[(size_t)c * 514 + 513];
    #pragma unroll
    for (int r = 0; r < 16; r++) acc[r] += w512 * cosv[r] + w513 * awv[r];

    float fbv = fb[c];
    float owv = ow[c];
    #pragma unroll
    for (int r = 0; r < 16; r++) {
        float gv = fmaxf(acc[r] + fbv, 0.f) * owv;
        gv = warpSum(gv);
        if (lane == 0) red2[r][w] = gv;
    }
    __syncthreads();
    if (tid < 16) {
        float s = 0.f;
        #pragma unroll
        for (int ww = 0; ww < 8; ww++) s += red2[tid][ww];
        int j = j0 + tid;
        if (j < NS) out[j] = s + obp[0] + 0.5f * cosv[tid];
    }
}

// ---------------- launch ----------------
extern "C" void kernel_launch(void* const* d_in, const int* in_sizes, int n_in,
                              void* d_out, int out_size)
{
    const float* emb    = (const float*)d_in[0];
    const int*   adj    = (const int*)  d_in[1];
    const float* proj_w = (const float*)d_in[3];
    const float* proj_b = (const float*)d_in[4];
    const float* ln_s   = (const float*)d_in[5];
    const float* ln_b   = (const float*)d_in[6];
    const float* gat_W  = (const float*)d_in[7];
    const float* gat_a  = (const float*)d_in[8];
    const float* fw     = (const float*)d_in[9];
    const float* fb     = (const float*)d_in[10];
    const float* ow     = (const float*)d_in[11];
    const float* ob     = (const float*)d_in[12];
    float* out = (float*)d_out;

    float *hP, *whP;
    cudaGetSymbolAddress((void**)&hP,  g_h);
    cudaGetSymbolAddress((void**)&whP, g_Wh);

    cudaFuncSetAttribute(attn_tc, cudaFuncAttributeMaxDynamicSharedMemorySize, SM_TOTAL);
    cudaFuncSetAttribute(gemm_tc<EMB>, cudaFuncAttributeMaxDynamicSharedMemorySize, GM_TOTAL);
    cudaFuncSetAttribute(gemm_tc<HID>, cudaFuncAttributeMaxDynamicSharedMemorySize, GM_TOTAL);

    gemm_tc<EMB><<<(T_N / 128) * 4, 256, GM_TOTAL>>>(emb, proj_w, proj_b, hP, 1,
                                                      nullptr, nullptr, nullptr);
    cos_update<<<(NS + 7) / 8, 256>>>();

    for (int L = 0; L < 2; L++) {
        ln_stats<<<T_N / 8, 256>>>();
        gemm_tc<HID><<<(T_N / 128) * 4, 256, GM_TOTAL>>>(hP, gat_W + (size_t)L * HID * HID,
                                                          nullptr, whP, 0,
                                                          gat_a + L * NH * 2 * HD,
                                                          ln_s + L * HID, ln_b + L * HID);
        attn_tc<<<128, 256, SM_TOTAL>>>(adj);
    }

    scorecos_k<<<(NS + 7) / 8, 256>>>();
    softmax_k<<<1, 1024>>>();
    fusion_k<<<(NS + 15) / 16, 256>>>(fw, fb, ow, ob, out);
}

// round 15
// speedup vs baseline: 1.5411x; 1.0361x over previous
#include <cuda_runtime.h>
#include <math.h>
#include <cstdint>

#define T_N  4096
#define EMB  384
#define HID  256
#define NH   4
#define HD   64
#define MD   32
#define S0   33
#define NS   4063

#if defined(__CUDA_ARCH_FEAT_SM103_ALL) || defined(__CUDA_ARCH_FEAT_SM100_ALL) || defined(__CUDA_ARCH_FEAT_SM101_ALL)
#define HAS_TC 1
#else
#define HAS_TC 0
#endif

__device__ float g_h  [T_N * HID];
__device__ float g_Wh [T_N * HID];
__device__ float g_src[NH * T_N];
__device__ float g_dst[NH * T_N];
__device__ float g_lnmu[T_N];
__device__ float g_lnrs[T_N];
__device__ float g_scores[NS];
__device__ float g_cosf[NS];
__device__ float g_aw[NS];

__device__ __forceinline__ float warpSum(float v) {
    #pragma unroll
    for (int o = 16; o; o >>= 1) v += __shfl_xor_sync(0xffffffffu, v, o);
    return v;
}
__device__ __forceinline__ float warpMax(float v) {
    #pragma unroll
    for (int o = 16; o; o >>= 1) v = fmaxf(v, __shfl_xor_sync(0xffffffffu, v, o));
    return v;
}
__device__ float blockSum256(float v) {
    __shared__ float sh[8];
    int w = threadIdx.x >> 5, l = threadIdx.x & 31;
    v = warpSum(v);
    if (l == 0) sh[w] = v;
    __syncthreads();
    float s = (threadIdx.x < 8) ? sh[threadIdx.x] : 0.f;
    if (w == 0) { s = warpSum(s); if (l == 0) sh[0] = s; }
    __syncthreads();
    float r = sh[0];
    __syncthreads();
    return r;
}

__device__ __forceinline__ uint32_t s2u(const void* p) {
    uint32_t a;
    asm("{ .reg .u64 t; cvta.to.shared.u64 t, %1; cvt.u32.u64 %0, t; }"
        : "=r"(a) : "l"(p));
    return a;
}
__device__ __forceinline__ float ex2f(float x) {
    float r;
    asm("ex2.approx.f32 %0, %1;" : "=f"(r) : "f"(x));
    return r;
}

#if HAS_TC
__device__ __forceinline__ uint32_t elect_one() {
    uint32_t pred;
    asm volatile("{\n\t.reg .pred p;\n\telect.sync _|p, 0xFFFFFFFF;\n\t"
                 "selp.b32 %0, 1, 0, p;\n\t}" : "=r"(pred));
    return pred;
}
__device__ __forceinline__ void mbar_init(uint32_t addr, uint32_t cnt) {
    asm volatile("mbarrier.init.shared.b64 [%0], %1;" :: "r"(addr), "r"(cnt) : "memory");
}
__device__ __forceinline__ void mbar_wait(uint32_t addr, uint32_t parity) {
    asm volatile(
        "{\n\t.reg .pred P;\n\t"
        "WL%=:\n\t"
        "mbarrier.try_wait.parity.acquire.cta.shared::cta.b64 P, [%0], %1, 0x989680;\n\t"
        "@P bra WD%=;\n\t"
        "bra WL%=;\n\t"
        "WD%=:\n\t}"
        :: "r"(addr), "r"(parity) : "memory");
}
__device__ __forceinline__ void sts_tf32(uint32_t addr, float v) {
    uint32_t t;
    asm("cvt.rn.tf32.f32 %0, %1;" : "=r"(t) : "f"(v));
    asm volatile("st.shared.b32 [%0], %1;" :: "r"(addr), "r"(t) : "memory");
}
__device__ __forceinline__ void sts4_tf32(uint32_t addr, float4 v) {
    uint32_t a, b, c, d;
    asm("cvt.rn.tf32.f32 %0, %1;" : "=r"(a) : "f"(v.x));
    asm("cvt.rn.tf32.f32 %0, %1;" : "=r"(b) : "f"(v.y));
    asm("cvt.rn.tf32.f32 %0, %1;" : "=r"(c) : "f"(v.z));
    asm("cvt.rn.tf32.f32 %0, %1;" : "=r"(d) : "f"(v.w));
    asm volatile("st.shared.v4.b32 [%0], {%1, %2, %3, %4};"
                 :: "r"(addr), "r"(a), "r"(b), "r"(c), "r"(d) : "memory");
}
__device__ __forceinline__ void mma_tf32_ss(uint32_t d_tmem, uint64_t a_desc,
                                            uint64_t b_desc, uint32_t idesc,
                                            uint32_t en) {
    asm volatile(
        "{\n\t.reg .pred p;\n\tsetp.ne.u32 p, %4, 0;\n\t"
        "tcgen05.mma.cta_group::1.kind::tf32 [%0], %1, %2, %3, {%5, %5, %5, %5}, p;\n\t}"
        :: "r"(d_tmem), "l"(a_desc), "l"(b_desc), "r"(idesc), "r"(en), "r"(0u)
        : "memory");
}
__device__ __forceinline__ void tc_commit(uint32_t mbar) {
    asm volatile(
        "tcgen05.commit.cta_group::1.mbarrier::arrive::one.shared::cluster.b64 [%0];"
        :: "r"(mbar) : "memory");
}
#define TC_LD_X32(r, tmem_addr) \
    asm volatile( \
        "tcgen05.ld.sync.aligned.32x32b.x32.b32 " \
        "{%0, %1, %2, %3, %4, %5, %6, %7, " \
        " %8, %9, %10, %11, %12, %13, %14, %15, " \
        " %16, %17, %18, %19, %20, %21, %22, %23, " \
        " %24, %25, %26, %27, %28, %29, %30, %31}, [%32];" \
        : "=r"((r)[0]),  "=r"((r)[1]),  "=r"((r)[2]),  "=r"((r)[3]), \
          "=r"((r)[4]),  "=r"((r)[5]),  "=r"((r)[6]),  "=r"((r)[7]), \
          "=r"((r)[8]),  "=r"((r)[9]),  "=r"((r)[10]), "=r"((r)[11]), \
          "=r"((r)[12]), "=r"((r)[13]), "=r"((r)[14]), "=r"((r)[15]), \
          "=r"((r)[16]), "=r"((r)[17]), "=r"((r)[18]), "=r"((r)[19]), \
          "=r"((r)[20]), "=r"((r)[21]), "=r"((r)[22]), "=r"((r)[23]), \
          "=r"((r)[24]), "=r"((r)[25]), "=r"((r)[26]), "=r"((r)[27]), \
          "=r"((r)[28]), "=r"((r)[29]), "=r"((r)[30]), "=r"((r)[31]) \
        : "r"(tmem_addr))
#endif // HAS_TC

#define DESC_BASE ((2ull << 61) | (1ull << 46) | (64ull << 32) | (1ull << 16))
#define TF32_IDESC ((1u << 4) | (2u << 7) | (2u << 10) | (8u << 17) | (8u << 24))

// attn smem: 4-deep ring
#define SM_PB(b) ((b) * 16384)
#define SM_BB(b) (65536 + (b) * 8192)
#define SM_TPTR  98304
#define SM_MB(b) (98320 + (b) * 8)
#define SM_ZF    98368
#define SM_TOTAL (98880 + 1024)

// gemm_tc smem
#define GM_AB(b)  ((b) * 16384)
#define GM_BB(b)  (32768 + (b) * 8192)
#define GM_TPTR   49152
#define GM_MB(b)  (49168 + (b) * 8)
#define GM_BIAS   49184
#define GM_GA     49440
#define GM_LNS    49952
#define GM_LNB    50976
#define GM_TOTAL  (52000 + 1024)

// ============== per-row LN stats ==============
__global__ void __launch_bounds__(256) ln_stats()
{
    int tid = threadIdx.x, w = tid >> 5, l = tid & 31;
    int row = blockIdx.x * 8 + w;
    const float* hp = &g_h[(size_t)row * HID];
    float v[8];
    float s = 0.f;
    #pragma unroll
    for (int e = 0; e < 8; e++) { v[e] = hp[l + 32 * e]; s += v[e]; }
    float mu = warpSum(s) * (1.f / HID);
    float ss = 0.f;
    #pragma unroll
    for (int e = 0; e < 8; e++) { float d = v[e] - mu; ss += d * d; }
    float rs = rsqrtf(warpSum(ss) * (1.f / HID) + 1e-5f);
    if (l == 0) { g_lnmu[row] = mu; g_lnrs[row] = rs; }
}

// ============== tcgen05 tf32 GEMM + LN-on-A + src/dst epilogue (R14) ==============
template<int K>
__global__ void __launch_bounds__(256) gemm_tc(const float* __restrict__ A,
                                               const float* __restrict__ Wt,
                                               const float* __restrict__ bias,
                                               float* __restrict__ C,
                                               int doRelu,
                                               const float* __restrict__ ga,
                                               const float* __restrict__ lnS,
                                               const float* __restrict__ lnB)
{
    extern __shared__ char dsm[];
    uint32_t raw = s2u(dsm);
    uint32_t base = (raw + 1023u) & ~1023u;
    char* smc = dsm + (base - raw);

    int tid = threadIdx.x, w = tid >> 5, lane = tid & 31;
    int cb = blockIdx.x & 3;
    int r0 = (blockIdx.x >> 2) * 128;
    int c0 = cb * 64;
    const int NC = K / 32;

#if HAS_TC
    if (w == 0)
        asm volatile("tcgen05.alloc.cta_group::1.sync.aligned.shared::cta.b32 [%0], %1;"
                     :: "r"(base + GM_TPTR), "r"(64u) : "memory");
    if (tid == 0) { mbar_init(base + GM_MB(0), 1); mbar_init(base + GM_MB(1), 1); }
    if (tid < 64) ((float*)(smc + GM_BIAS))[tid] = bias ? bias[c0 + tid] : 0.f;
    if (ga && tid < 128) ((float*)(smc + GM_GA))[tid] = ga[cb * 2 * HD + tid];
    if (lnS) {
        ((float*)(smc + GM_LNS))[tid] = lnS[tid & (HID - 1)];
        ((float*)(smc + GM_LNB))[tid] = lnB[tid & (HID - 1)];
    }
    __syncthreads();
    uint32_t tmem;
    asm volatile("ld.shared.b32 %0, [%1];" : "=r"(tmem) : "r"(base + GM_TPTR));

    uint32_t aoff[4];
    int ak4[4];
    const float4* aptr[4];
    float4 av4[4];
    float muv[4], rsv[4];
    #pragma unroll
    for (int q = 0; q < 4; q++) {
        int idx = tid + q * 256;
        int m = idx >> 3, k4 = (idx & 7) * 4;
        aoff[q] = (uint32_t)(m * 128) + (((uint32_t)(k4 * 4)) ^ (uint32_t)((m & 7) << 4));
        ak4[q] = k4;
        aptr[q] = (const float4*)(A + (size_t)(r0 + m) * K + k4);
        av4[q] = aptr[q][0];
        if (lnS) { muv[q] = g_lnmu[r0 + m]; rsv[q] = g_lnrs[r0 + m]; }
    }
    uint32_t boff[2];
    const float4* bptr[2];
    float4 bv4[2];
    #pragma unroll
    for (int q = 0; q < 2; q++) {
        int idx = tid + q * 256;
        int n = idx >> 3, k4 = (idx & 7) * 4;
        boff[q] = (uint32_t)(n * 128) + (((uint32_t)(k4 * 4)) ^ (uint32_t)((n & 7) << 4));
        bptr[q] = (const float4*)(Wt + (size_t)(c0 + n) * K + k4);
        bv4[q] = bptr[q][0];
    }

    int wp0 = 0, wp1 = 0;
    for (int t = 0; t < NC; t++) {
        int buf = t & 1;
        uint32_t Ab = base + GM_AB(buf);
        uint32_t Bb = base + GM_BB(buf);
        uint32_t mb = base + GM_MB(buf);

        if (t >= 2) {
            if (buf == 0) { mbar_wait(base + GM_MB(0), wp0); wp0 ^= 1; }
            else          { mbar_wait(base + GM_MB(1), wp1); wp1 ^= 1; }
        }

        #pragma unroll
        for (int q = 0; q < 4; q++) {
            float4 x = av4[q];
            if (lnS) {
                int k = t * 32 + ak4[q];
                float4 sc = *(const float4*)(smc + GM_LNS + (size_t)k * 4);
                float4 bi = *(const float4*)(smc + GM_LNB + (size_t)k * 4);
                x.x = (x.x - muv[q]) * rsv[q] * sc.x + bi.x;
                x.y = (x.y - muv[q]) * rsv[q] * sc.y + bi.y;
                x.z = (x.z - muv[q]) * rsv[q] * sc.z + bi.z;
                x.w = (x.w - muv[q]) * rsv[q] * sc.w + bi.w;
            }
            sts4_tf32(Ab + aoff[q], x);
        }
        #pragma unroll
        for (int q = 0; q < 2; q++) sts4_tf32(Bb + boff[q], bv4[q]);

        if (t < NC - 1) {
            #pragma unroll
            for (int q = 0; q < 4; q++) { aptr[q] += 8; av4[q] = aptr[q][0]; }
            #pragma unroll
            for (int q = 0; q < 2; q++) { bptr[q] += 8; bv4[q] = bptr[q][0]; }
        }

        asm volatile("fence.proxy.async.shared::cta;" ::: "memory");
        __syncthreads();

        if (w == 0 && elect_one()) {
            uint64_t ad = DESC_BASE | ((uint64_t)(Ab >> 4) & 0x3FFF);
            uint64_t bd = DESC_BASE | ((uint64_t)(Bb >> 4) & 0x3FFF);
            #pragma unroll
            for (int c = 0; c < 4; c++)
                mma_tf32_ss(tmem, ad + c * 2, bd + c * 2, TF32_IDESC,
                            (t > 0 || c > 0) ? 1u : 0u);
            tc_commit(mb);
        }
    }

    mbar_wait(base + GM_MB(1), wp1);
    asm volatile("tcgen05.fence::after_thread_sync;" ::: "memory");

    if (w < 4) {
        uint32_t dr[64];
        TC_LD_X32(dr, tmem);
        TC_LD_X32(dr + 32, tmem + 32);
        asm volatile("tcgen05.wait::ld.sync.aligned;" ::: "memory");
        int row = w * 32 + lane;
        const float* sb = (const float*)(smc + GM_BIAS);
        float4* op = (float4*)&C[(size_t)(r0 + row) * HID + c0];
        float vals[64];
        #pragma unroll
        for (int q = 0; q < 16; q++) {
            float4 o;
            o.x = __uint_as_float(dr[4 * q])     + sb[4 * q];
            o.y = __uint_as_float(dr[4 * q + 1]) + sb[4 * q + 1];
            o.z = __uint_as_float(dr[4 * q + 2]) + sb[4 * q + 2];
            o.w = __uint_as_float(dr[4 * q + 3]) + sb[4 * q + 3];
            if (doRelu) {
                o.x = fmaxf(o.x, 0.f); o.y = fmaxf(o.y, 0.f);
                o.z = fmaxf(o.z, 0.f); o.w = fmaxf(o.w, 0.f);
            }
            vals[4 * q] = o.x; vals[4 * q + 1] = o.y;
            vals[4 * q + 2] = o.z; vals[4 * q + 3] = o.w;
            op[q] = o;
        }
        if (ga) {
            const float* as = (const float*)(smc + GM_GA);
            const float* ad = as + HD;
            float ssum = 0.f, dsum = 0.f;
            #pragma unroll
            for (int c = 0; c < 64; c++) {
                ssum += vals[c] * as[c];
                dsum += vals[c] * ad[c];
            }
            g_src[cb * T_N + r0 + row] = ssum;
            g_dst[cb * T_N + r0 + row] = dsum;
        }
    }
    __syncthreads();
    if (w == 0) {
        asm volatile("tcgen05.relinquish_alloc_permit.cta_group::1.sync.aligned;");
        asm volatile("tcgen05.dealloc.cta_group::1.sync.aligned.b32 %0, %1;"
                     :: "r"(tmem), "r"(64u));
    }
#else
    int c = tid & 63, rh = tid >> 6;
    for (int m = rh * 32; m < rh * 32 + 32; m++) {
        float acc = 0.f;
        const float* ap = A + (size_t)(r0 + m) * K;
        const float* wp2 = Wt + (size_t)(c0 + c) * K;
        float mu = lnS ? g_lnmu[r0 + m] : 0.f;
        float rs = lnS ? g_lnrs[r0 + m] : 1.f;
        for (int k = 0; k < K; k++) {
            float a = ap[k];
            if (lnS) a = (a - mu) * rs * lnS[k] + lnB[k];
            acc += a * wp2[k];
        }
        float b = bias ? bias[c0 + c] : 0.f;
        float v = acc + b;
        if (doRelu) v = fmaxf(v, 0.f);
        C[(size_t)(r0 + m) * HID + c0 + c] = v;
    }
    __syncthreads();
    if (ga && tid < 128) {
        int row = tid;
        const float* cp = &C[(size_t)(r0 + row) * HID + c0];
        float ssum = 0.f, dsum = 0.f;
        for (int cc = 0; cc < 64; cc++) {
            ssum += cp[cc] * ga[cb * 2 * HD + cc];
            dsum += cp[cc] * ga[cb * 2 * HD + HD + cc];
        }
        g_src[cb * T_N + r0 + row] = ssum;
        g_dst[cb * T_N + r0 + row] = dsum;
    }
#endif
}

__global__ void __launch_bounds__(256) cos_update()
{
    __shared__ float q[HID];
    int tid = threadIdx.x;
    q[tid] = g_h[tid];
    __syncthreads();
    float qn = blockSum256(q[tid] * q[tid]);
    float qinv = 1.f / (sqrtf(qn) + 1e-8f);
    int w = tid >> 5, l = tid & 31;
    int j = blockIdx.x * 8 + w;
    if (j >= NS) return;
    float* s = &g_h[(size_t)(S0 + j) * HID];
    float sv[8];
    float qs = 0.f, ss = 0.f;
    #pragma unroll
    for (int e = 0; e < 8; e++) {
        float x = s[l + 32 * e];
        sv[e] = x;
        qs += q[l + 32 * e] * x;
        ss += x * x;
    }
    qs = warpSum(qs);
    ss = warpSum(ss);
    float cs = qs * qinv / (sqrtf(ss) + 1e-8f);
    #pragma unroll
    for (int e = 0; e < 8; e++)
        s[l + 32 * e] = sv[e] + 0.8f * q[l + 32 * e] * cs;
}

// ============== attention: factored-exp P-gen (no inner MUFU) ==============
// p = exp(lrelu(src+dst)) = max(exp(src)exp(dst), exp(.2src)exp(.2dst))
__global__ void __launch_bounds__(256) attn_tc(const int* __restrict__ adj)
{
    extern __shared__ char dsm[];
    uint32_t raw = s2u(dsm);
    uint32_t base = (raw + 1023u) & ~1023u;
    char* smc = dsm + (base - raw);
    float* zfin = (float*)(smc + SM_ZF);

    int tid = threadIdx.x, w = tid >> 5, lane = tid & 31;
    int h = blockIdx.x & 3;
    int i0 = (blockIdx.x >> 2) * 128;

    const float L2E = 1.44269504f;
    float es[16], es2[16], zacc[16];
    #pragma unroll
    for (int i = 0; i < 16; i++) {
        float s = g_src[h * T_N + i0 + w * 16 + i];
        es[i]  = ex2f(s * L2E);
        es2[i] = ex2f(s * (0.2f * L2E));
        zacc[i] = 0.f;
    }

    const int* adjp = adj + (size_t)(i0 + w * 16) * T_N + lane;
    const float* dstp = g_dst + h * T_N + lane;
    const float* whp0 = g_Wh + h * 64;
    const int NT = T_N / 32;

    int av[16];
    float dval;
    #pragma unroll
    for (int i = 0; i < 16; i++) av[i] = adjp[(size_t)i * T_N];
    dval = dstp[0];

#if HAS_TC
    if (w == 0)
        asm volatile("tcgen05.alloc.cta_group::1.sync.aligned.shared::cta.b32 [%0], %1;"
                     :: "r"(base + SM_TPTR), "r"(64u) : "memory");
    if (tid == 0) {
        #pragma unroll
        for (int b = 0; b < 4; b++) mbar_init(base + SM_MB(b), 1);
    }
    __syncthreads();
    uint32_t tmem;
    asm volatile("ld.shared.b32 %0, [%1];" : "=r"(tmem) : "r"(base + SM_TPTR));

    uint32_t boffq[8];
    const float* bptr[8];
    #pragma unroll
    for (int q = 0; q < 8; q++) {
        int idx = tid + q * 256;
        int n = idx & 63, k = idx >> 6;
        boffq[q] = (uint32_t)(n * 128) + (((uint32_t)(k * 4)) ^ (uint32_t)((n & 7) << 4));
        bptr[q] = whp0 + (size_t)k * HID + n;
    }
    float bv[8];
    #pragma unroll
    for (int q = 0; q < 8; q++) bv[q] = bptr[q][0];

    int wpar0 = 0, wpar1 = 0, wpar2 = 0, wpar3 = 0;

    for (int tb = 0; tb < NT; tb += 4) {
        #pragma unroll
        for (int b = 0; b < 4; b++) {
            const int t = tb + b;
            uint32_t Pb = base + SM_PB(b);
            uint32_t Bb = base + SM_BB(b);
            uint32_t mb = base + SM_MB(b);

            if (tb > 0) {
                if (b == 0)      { mbar_wait(mb, wpar0); wpar0 ^= 1; }
                else if (b == 1) { mbar_wait(mb, wpar1); wpar1 ^= 1; }
                else if (b == 2) { mbar_wait(mb, wpar2); wpar2 ^= 1; }
                else             { mbar_wait(mb, wpar3); wpar3 ^= 1; }
            }

            #pragma unroll
            for (int q = 0; q < 8; q++) sts_tf32(Bb + boffq[q], bv[q]);

            // per-tile lane exponentials (2 MUFU)
            float ed  = ex2f(dval * L2E);
            float ed2 = ex2f(dval * (0.2f * L2E));

            #pragma unroll
            for (int i = 0; i < 16; i++) {
                float p = fmaxf(es[i] * ed, es2[i] * ed2);
                p = av[i] ? p : 0.f;
                zacc[i] += p;
                sts_tf32(Pb + (uint32_t)((w * 16 + i) * 128)
                            + ((uint32_t)(lane * 4) ^ (uint32_t)((i & 7) << 4)), p);
            }

            if (t < NT - 1) {
                int j1 = (t + 1) * 32;
                #pragma unroll
                for (int i = 0; i < 16; i++) av[i] = adjp[(size_t)i * T_N + j1];
                dval = dstp[j1];
                #pragma unroll
                for (int q = 0; q < 8; q++) {
                    bptr[q] += 32 * HID;
                    bv[q] = bptr[q][0];
                }
            }

            asm volatile("fence.proxy.async.shared::cta;" ::: "memory");
            __syncthreads();

            if (w == 0 && elect_one()) {
                uint64_t ad = DESC_BASE | ((uint64_t)(Pb >> 4) & 0x3FFF);
                uint64_t bd = DESC_BASE | ((uint64_t)(Bb >> 4) & 0x3FFF);
                #pragma unroll
                for (int c = 0; c < 4; c++)
                    mma_tf32_ss(tmem, ad + c * 2, bd + c * 2, TF32_IDESC,
                                (t > 0 || c > 0) ? 1u : 0u);
                tc_commit(mb);
            }
        }
    }

    #pragma unroll
    for (int i = 0; i < 16; i++) {
        float z = warpSum(zacc[i]);
        if (lane == i) zfin[w * 16 + i] = 1.f / z;
    }
    __syncthreads();

    mbar_wait(base + SM_MB(3), wpar3);
    asm volatile("tcgen05.fence::after_thread_sync;" ::: "memory");

    if (w < 4) {
        uint32_t dr[64];
        TC_LD_X32(dr, tmem);
        TC_LD_X32(dr + 32, tmem + 32);
        asm volatile("tcgen05.wait::ld.sync.aligned;" ::: "memory");
        int row = w * 32 + lane;
        float zi = zfin[row];
        float4* hp = (float4*)&g_h[(size_t)(i0 + row) * HID + h * 64];
        #pragma unroll
        for (int q = 0; q < 16; q++) {
            float4 old = hp[q];
            float4 o;
            o.x = 0.5f * fmaxf(__uint_as_float(dr[4 * q])     * zi, 0.f) + 0.5f * old.x;
            o.y = 0.5f * fmaxf(__uint_as_float(dr[4 * q + 1]) * zi, 0.f) + 0.5f * old.y;
            o.z = 0.5f * fmaxf(__uint_as_float(dr[4 * q + 2]) * zi, 0.f) + 0.5f * old.z;
            o.w = 0.5f * fmaxf(__uint_as_float(dr[4 * q + 3]) * zi, 0.f) + 0.5f * old.w;
            hp[q] = o;
        }
    }
    __syncthreads();
    if (w == 0) {
        asm volatile("tcgen05.relinquish_alloc_permit.cta_group::1.sync.aligned;");
        asm volatile("tcgen05.dealloc.cta_group::1.sync.aligned.b32 %0, %1;"
                     :: "r"(tmem), "r"(64u));
    }
#else
    // SIMT fallback (non-sm_103a passes only)
    float* P = (float*)smc;
    int col = tid & 63, rhalf = tid >> 6;
    float acc[32];
    #pragma unroll
    for (int r = 0; r < 32; r++) acc[r] = 0.f;
    __syncthreads();

    for (int t = 0; t < NT; t++) {
        int j0 = t * 32;
        float ed  = ex2f(dval * L2E);
        float ed2 = ex2f(dval * (0.2f * L2E));
        #pragma unroll
        for (int i = 0; i < 16; i++) {
            float p = fmaxf(es[i] * ed, es2[i] * ed2);
            p = av[i] ? p : 0.f;
            zacc[i] += p;
            P[(w * 16 + i) * 33 + lane] = p;
        }
        if (t < NT - 1) {
            #pragma unroll
            for (int i = 0; i < 16; i++) av[i] = adjp[(size_t)i * T_N + j0 + 32];
            dval = dstp[j0 + 32];
        }
        __syncthreads();
        const float* whc = whp0 + (size_t)j0 * HID + col;
        #pragma unroll 4
        for (int jl = 0; jl < 32; jl++) {
            float b = whc[(size_t)jl * HID];
            const float* Pc = P + (rhalf * 32) * 33 + jl;
            #pragma unroll
            for (int r = 0; r < 32; r++) acc[r] += Pc[r * 33] * b;
        }
        __syncthreads();
    }

    #pragma unroll
    for (int i = 0; i < 16; i++) {
        float z = warpSum(zacc[i]);
        if (lane == i) zfin[w * 16 + i] = 1.f / z;
    }
    __syncthreads();
    #pragma unroll
    for (int r = 0; r < 32; r++) {
        int row = rhalf * 32 + r;
        size_t gi = (size_t)(i0 + row) * HID + h * 64 + col;
        float o = acc[r] * zfin[row];
        g_h[gi] = 0.5f * fmaxf(o, 0.f) + 0.5f * g_h[gi];
    }
#endif
}

__global__ void __launch_bounds__(256) scorecos_k()
{
    __shared__ float q[HID];
    int tid = threadIdx.x;
    q[tid] = g_h[tid];
    __syncthreads();
    float qn = blockSum256(q[tid] * q[tid]);
    float qinv = 1.f / (sqrtf(qn) + 1e-8f);
    int w = tid >> 5, l = tid & 31;
    int j = blockIdx.x * 8 + w;
    if (j >= NS) return;
    const float* s = &g_h[(size_t)(S0 + j) * HID];
    float qs = 0.f, ss = 0.f;
    #pragma unroll
    for (int e = 0; e < 8; e++) {
        float x = s[l + 32 * e];
        qs += q[l + 32 * e] * x;
        ss += x * x;
    }
    qs = warpSum(qs);
    ss = warpSum(ss);
    if (l == 0) {
        g_scores[j] = qs * (1.0f / 16.0f);
        g_cosf[j] = qs * qinv / (sqrtf(ss) + 1e-8f);
    }
}

__global__ void __launch_bounds__(1024) softmax_k()
{
    __shared__ float sh[32];
    int tid = threadIdx.x, w = tid >> 5, l = tid & 31;

    float m = -1e30f;
    for (int i = tid; i < NS; i += 1024) m = fmaxf(m, g_scores[i]);
    m = warpMax(m);
    if (l == 0) sh[w] = m;
    __syncthreads();
    if (w == 0) { float mm = sh[l]; mm = warpMax(mm); if (l == 0) sh[0] = mm; }
    __syncthreads();
    m = sh[0];
    __syncthreads();

    float sum = 0.f;
    for (int i = tid; i < NS; i += 1024) {
        float e = __expf(g_scores[i] - m);
        g_aw[i] = e;
        sum += e;
    }
    sum = warpSum(sum);
    if (l == 0) sh[w] = sum;
    __syncthreads();
    if (w == 0) { float ss = sh[l]; ss = warpSum(ss); if (l == 0) sh[0] = ss; }
    __syncthreads();
    float inv = 1.f / sh[0];
    for (int i = tid; i < NS; i += 1024) g_aw[i] *= inv;
}

__global__ void __launch_bounds__(256) fusion_k(const float* __restrict__ fw,
                                                const float* __restrict__ fb,
                                                const float* __restrict__ ow,
                                                const float* __restrict__ obp,
                                                float* __restrict__ out)
{
    __shared__ float fws[256][33];
    __shared__ __align__(16) float feat_s[32][20];
    __shared__ float awv[16], cosv[16];
    __shared__ float red2[16][8];
    int tid = threadIdx.x;
    int w = tid >> 5, lane = tid & 31;
    int j0 = blockIdx.x * 16;

    if (tid < 16) {
        int j = j0 + tid;
        awv[tid]  = (j < NS) ? g_aw[j]   : 0.f;
        cosv[tid] = (j < NS) ? g_cosf[j] : 0.f;
    }
    __syncthreads();

    unsigned long long acc2[8];
    #pragma unroll
    for (int i = 0; i < 8; i++) acc2[i] = 0ull;
    int c = tid;

    for (int k0 = 0; k0 < 512; k0 += 32) {
        #pragma unroll 8
        for (int rr = 0; rr < 32; rr++)
            fws[w * 32 + rr][lane] = fw[(size_t)(w * 32 + rr) * 514 + k0 + lane];
        #pragma unroll
        for (int q = 0; q < 2; q++) {
            int idx = tid + q * 256;
            int r = idx >> 5, kk = idx & 31;
            int k = k0 + kk;
            int j = j0 + r;
            float v = 0.f;
            if (j < NS) {
                if (k < 256) v = g_h[(size_t)(S0 + j) * HID + k];
                else         v = g_h[k - 256] * (awv[r] + 0.5f);
            }
            feat_s[kk][r] = v;
        }
        __syncthreads();

        #pragma unroll 8
        for (int kk = 0; kk < 32; kk++) {
            float wv = fws[c][kk];
            unsigned long long wvd;
            asm("mov.b64 %0, {%1,%1};" : "=l"(wvd) : "r"(__float_as_uint(wv)));
            const ulonglong2* fp = (const ulonglong2*)&feat_s[kk][0];
            #pragma unroll
            for (int q = 0; q < 4; q++) {
                ulonglong2 fv = fp[q];
                asm("fma.rn.f32x2 %0, %1, %2, %0;" : "+l"(acc2[2*q  ]) : "l"(fv.x), "l"(wvd));
                asm("fma.rn.f32x2 %0, %1, %2, %0;" : "+l"(acc2[2*q+1]) : "l"(fv.y), "l"(wvd));
            }
        }
        __syncthreads();
    }

    float acc[16];
    #pragma unroll
    for (int q = 0; q < 8; q++) {
        acc[2*q]   = __uint_as_float((unsigned)(acc2[q] & 0xffffffffull));
        acc[2*q+1] = __uint_as_float((unsigned)(acc2[q] >> 32));
    }
    float w512 = fw[(size_t)c * 514 + 512];
    float w513 = fw[(size_t)c * 514 + 513];
    #pragma unroll
    for (int r = 0; r < 16; r++) acc[r] += w512 * cosv[r] + w513 * awv[r];

    float fbv = fb[c];
    float owv = ow[c];
    #pragma unroll
    for (int r = 0; r < 16; r++) {
        float gv = fmaxf(acc[r] + fbv, 0.f) * owv;
        gv = warpSum(gv);
        if (lane == 0) red2[r][w] = gv;
    }
    __syncthreads();
    if (tid < 16) {
        float s = 0.f;
        #pragma unroll
        for (int ww = 0; ww < 8; ww++) s += red2[tid][ww];
        int j = j0 + tid;
        if (j < NS) out[j] = s + obp[0] + 0.5f * cosv[tid];
    }
}

// ---------------- launch ----------------
extern "C" void kernel_launch(void* const* d_in, const int* in_sizes, int n_in,
                              void* d_out, int out_size)
{
    const float* emb    = (const float*)d_in[0];
    const int*   adj    = (const int*)  d_in[1];
    const float* proj_w = (const float*)d_in[3];
    const float* proj_b = (const float*)d_in[4];
    const float* ln_s   = (const float*)d_in[5];
    const float* ln_b   = (const float*)d_in[6];
    const float* gat_W  = (const float*)d_in[7];
    const float* gat_a  = (const float*)d_in[8];
    const float* fw     = (const float*)d_in[9];
    const float* fb     = (const float*)d_in[10];
    const float* ow     = (const float*)d_in[11];
    const float* ob     = (const float*)d_in[12];
    float* out = (float*)d_out;

    float *hP, *whP;
    cudaGetSymbolAddress((void**)&hP,  g_h);
    cudaGetSymbolAddress((void**)&whP, g_Wh);

    cudaFuncSetAttribute(attn_tc, cudaFuncAttributeMaxDynamicSharedMemorySize, SM_TOTAL);
    cudaFuncSetAttribute(gemm_tc<EMB>, cudaFuncAttributeMaxDynamicSharedMemorySize, GM_TOTAL);
    cudaFuncSetAttribute(gemm_tc<HID>, cudaFuncAttributeMaxDynamicSharedMemorySize, GM_TOTAL);

    gemm_tc<EMB><<<(T_N / 128) * 4, 256, GM_TOTAL>>>(emb, proj_w, proj_b, hP, 1,
                                                      nullptr, nullptr, nullptr);
    cos_update<<<(NS + 7) / 8, 256>>>();

    for (int L = 0; L < 2; L++) {
        ln_stats<<<T_N / 8, 256>>>();
        gemm_tc<HID><<<(T_N / 128) * 4, 256, GM_TOTAL>>>(hP, gat_W + (size_t)L * HID * HID,
                                                          nullptr, whP, 0,
                                                          gat_a + L * NH * 2 * HD,
                                                          ln_s + L * HID, ln_b + L * HID);
        attn_tc<<<128, 256, SM_TOTAL>>>(adj);
    }

    scorecos_k<<<(NS + 7) / 8, 256>>>();
    softmax_k<<<1, 1024>>>();
    fusion_k<<<(NS + 15) / 16, 256>>>(fw, fb, ow, ob, out);
}